// round 13
// baseline (speedup 1.0000x reference)
#include <cuda_runtime.h>
#include <math.h>
#include <float.h>
#include <stdint.h>
#include <mma.h>

using namespace nvcuda;

#define S_SLOTS 65536
#define DIM     512
#define BATCH   64

#define LDA  36
#define LDB  36
#define LDD  100
#define STAGE_FLOATS ((128 + 96) * 36)
#define RING_FLOATS  (3 * STAGE_FLOATS)
#define RING_BYTES   (RING_FLOATS * 4)

// ---------------- device scratch ----------------
__device__ float g_B[96 * DIM];
__device__ float g_sims[(size_t)BATCH * S_SLOTS];
__device__ float g_confdot[(size_t)S_SLOTS * 32];
__device__ float g_norms[S_SLOTS];
__device__ float g_erase[S_SLOTS];
__device__ float g_maskedpre[S_SLOTS];
__device__ float g_slotage[S_SLOTS];
__device__ unsigned g_bmax[BATCH];
__device__ float g_storev[BATCH];
__device__ int   g_ti[BATCH * 3];
__device__ float g_tv[BATCH * 3];
__device__ float g_p3v[BATCH * 4 * 3];
__device__ int   g_p3i[BATCH * 4 * 3];
__device__ float g_pairacc[BATCH * 3 * 2];
__device__ float g_strength[BATCH * 3];
__device__ int   g_apply[BATCH * 3];
__device__ float g_drifted0[DIM];
__device__ int   g_chg[256];
__device__ int   g_nchg;
__device__ unsigned g_cnt_main, g_cnt_scan, g_cnt_pair;

struct Scalars {
    float stepf;
    int   n_active;
    unsigned int age_max_bits;
    unsigned long long victim_pack;
    int   cond_count;
    unsigned int masked_max_bits;
    unsigned long long wpack_m;
    unsigned long long wpack_a;
    int   do_erase;
    int   victim;
    float dyn_thr, topk_thr, raw_thr;
    float nov_mean;
    int   should_store;
    int   use_slotage;
    int   write_idx;
};
__device__ Scalars g_s;

__device__ __forceinline__ float sigf(float x) { return 1.0f / (1.0f + __expf(-x)); }
__device__ __forceinline__ unsigned fenc(float f) {
    unsigned u = __float_as_uint(f);
    return (u & 0x80000000u) ? ~u : (u | 0x80000000u);
}
__device__ __forceinline__ float fdec(unsigned u) {
    return (u & 0x80000000u) ? __uint_as_float(u ^ 0x80000000u) : __uint_as_float(~u);
}
__device__ __forceinline__ bool better(float av, int ai, float bv, int bi) {
    return (av > bv) || (av == bv && ai < bi);
}
__device__ __forceinline__ void cp16(uint32_t dst_smem, const void* src) {
    asm volatile("cp.async.ca.shared.global [%0], [%1], 16;" :: "r"(dst_smem), "l"(src));
}
__device__ __forceinline__ void cp_commit() {
    asm volatile("cp.async.commit_group;");
}

// ---------------- 1: reset ----------------
__global__ void k_reset(const void* step_ptr) {
    int t = threadIdx.x;   // 384
    if (t == 0) {
        int   iv = *(const int*)step_ptr;
        float fv = *(const float*)step_ptr;
        g_s.stepf = (iv > 0 && iv < 100000000) ? (float)iv : fv;
        g_s.n_active = 0;
        g_s.age_max_bits = 0u;
        g_s.victim_pack = 0ull;
        g_s.cond_count = 0;
        g_s.masked_max_bits = 0u;
        g_s.wpack_m = 0ull;
        g_s.wpack_a = 0ull;
        g_cnt_main = 0u; g_cnt_scan = 0u; g_cnt_pair = 0u;
    }
    if (t < BATCH) g_bmax[t] = 0u;
    if (t < BATCH * 3 * 2) g_pairacc[t] = 0.f;
}

// ---------------- 2: setup: store gate (0..63) + B build (64..159) + agemax (160..415) ----------------
__global__ void k_setup(const float* __restrict__ nc, const float* __restrict__ q,
                        const float* __restrict__ at, const float* __restrict__ ec_w,
                        const float* __restrict__ sr_w1, const float* __restrict__ sr_b1,
                        const float* __restrict__ sr_g,  const float* __restrict__ sr_beta,
                        const float* __restrict__ sr_w2, const float* __restrict__ sr_b2,
                        const float* __restrict__ sn_w,  const float* __restrict__ sn_b,
                        const float* __restrict__ sg_w,  const float* __restrict__ sg_b,
                        float* __restrict__ out_store) {
    int bx = blockIdx.x, t = threadIdx.x;   // 256 threads

    if (bx >= 160) {
        // ---- agemax ----
        __shared__ unsigned shu[256];
        int s = (bx - 160) * 256 + t;
        float age = fmaxf(g_s.stepf - at[s], 0.f);
        shu[t] = __float_as_uint(age);
        __syncthreads();
        for (int off = 128; off > 0; off >>= 1) {
            if (t < off && shu[t + off] > shu[t]) shu[t] = shu[t + off];
            __syncthreads();
        }
        if (t == 0) atomicMax(&g_s.age_max_bits, shu[0]);
        return;
    }
    if (bx >= 64) {
        // ---- B build (local norm) ----
        int r = bx - 64;
        if (r < 64) {
            __shared__ float red[256];
            float v0 = nc[r * 512 + t];
            float v1 = nc[r * 512 + 256 + t];
            red[t] = v0 * v0 + v1 * v1;
            __syncthreads();
            for (int off = 128; off > 0; off >>= 1) { if (t < off) red[t] += red[t + off]; __syncthreads(); }
            float inv = 1.0f / fmaxf(sqrtf(red[0]), 1e-12f);
            g_B[r * DIM + t]       = wmma::__float_to_tf32(v0 * inv);
            g_B[r * DIM + 256 + t] = wmma::__float_to_tf32(v1 * inv);
        } else {
            int j = r - 64;
            for (int k = t; k < DIM; k += 256)
                g_B[r * DIM + k] = wmma::__float_to_tf32(ec_w[(size_t)k * 32 + j]);
        }
        return;
    }
    // ---- store gate (heavy, scheduled first) ----
    int b = bx;
    __shared__ float comb[1024];
    __shared__ float hpart[4][256];
    __shared__ float rh[256];
    __shared__ float red[256];
    __shared__ float r2part[2][128];
    __shared__ float nfpart[2][128];
    for (int i = t; i < 512; i += 256) {
        comb[i] = nc[b * 512 + i];
        comb[512 + i] = q[b * 512 + i];
    }
    __syncthreads();
    int ks = t >> 6, cg = t & 63;
    {
        float4 a = make_float4(0.f, 0.f, 0.f, 0.f);
        const float* wp = sr_w1 + 4 * cg;
        for (int k = ks * 256; k < ks * 256 + 256; k++) {
            float4 w = *(const float4*)(wp + (size_t)k * 256);
            float x = comb[k];
            a.x = fmaf(x, w.x, a.x); a.y = fmaf(x, w.y, a.y);
            a.z = fmaf(x, w.z, a.z); a.w = fmaf(x, w.w, a.w);
        }
        ((float4*)&hpart[ks][0])[cg] = a;
    }
    __syncthreads();
    float h = hpart[0][t] + hpart[1][t] + hpart[2][t] + hpart[3][t] + sr_b1[t];
    red[t] = h; __syncthreads();
    for (int off = 128; off > 0; off >>= 1) { if (t < off) red[t] += red[t + off]; __syncthreads(); }
    float m = red[0] / 256.0f; __syncthreads();
    float d = h - m;
    red[t] = d * d; __syncthreads();
    for (int off = 128; off > 0; off >>= 1) { if (t < off) red[t] += red[t + off]; __syncthreads(); }
    float var = red[0] / 256.0f; __syncthreads();
    float hn = d * rsqrtf(var + 1e-5f) * sr_g[t] + sr_beta[t];
    rh[t] = fmaxf(hn, 0.f);
    __syncthreads();
    {
        int ks2 = t >> 7, c = t & 127;
        float a = 0.f;
        for (int k = ks2 * 128; k < ks2 * 128 + 128; k++)
            a = fmaf(rh[k], sr_w2[(size_t)k * 128 + c], a);
        r2part[ks2][c] = a;
    }
    {
        int ks2 = t >> 7, c = t & 127;
        float a = 0.f;
        for (int k = ks2 * 256; k < ks2 * 256 + 256; k++)
            a = fmaf(comb[k], sn_w[(size_t)k * 128 + c], a);
        nfpart[ks2][c] = a;
    }
    __syncthreads();
    float val = 0.f;
    if (t < 128) {
        float r = fmaxf(r2part[0][t] + r2part[1][t] + sr_b2[t], 0.f);
        float nf = sigf(nfpart[0][t] + nfpart[1][t] + sn_b[t]);
        val = (r + nf) * sg_w[t];
    }
    red[t] = val; __syncthreads();
    for (int off = 128; off > 0; off >>= 1) { if (t < off) red[t] += red[t + off]; __syncthreads(); }
    if (t == 0) {
        float sc = sigf(red[0] + sg_b[0]);
        g_storev[b] = sc;
        out_store[b] = sc;
    }
}

// ---------------- 3: wmma tf32 GEMM (unchanged from 370.8 best) ----------------
__global__ void __launch_bounds__(256, 2) k_main(const float* __restrict__ mem,
                                                 const float* __restrict__ at,
                                                 float* __restrict__ out_mem,
                                                 float* __restrict__ out_nov) {
    extern __shared__ __align__(16) float ring[];
    __shared__ float nsh[128];
    __shared__ int shi[128];
    __shared__ unsigned long long shv[128];
    __shared__ bool sLast;

    const int t = threadIdx.x;
    const int wid = t >> 5, lid = t & 31;
    const int row0 = blockIdx.x * 128;
    const int wr = wid >> 1;
    const int wc = wid & 1;
    const int ra = t >> 3, fa = t & 7;

    uint32_t ring_sm = (uint32_t)__cvta_generic_to_shared(ring);

    wmma::fragment<wmma::accumulator, 16, 16, 8, float> acc[2][3];
#pragma unroll
    for (int i = 0; i < 2; i++)
#pragma unroll
        for (int j = 0; j < 3; j++) wmma::fill_fragment(acc[i][j], 0.0f);
    float sq[4] = {0.f, 0.f, 0.f, 0.f};

#pragma unroll
    for (int st = 0; st < 3; st++) {
        const int kc = st * 32;
        uint32_t base = ring_sm + st * (STAGE_FLOATS * 4);
#pragma unroll
        for (int u = 0; u < 4; u++) {
            int r = ra + 32 * u;
            cp16(base + (uint32_t)((r * LDA + fa * 4) * 4),
                 mem + (size_t)(row0 + r) * DIM + kc + fa * 4);
        }
#pragma unroll
        for (int u = 0; u < 3; u++) {
            int idx = t + 256 * u;
            int r = idx >> 3, f = idx & 7;
            cp16(base + (uint32_t)((128 * LDA + r * LDB + f * 4) * 4),
                 g_B + (size_t)r * DIM + kc + f * 4);
        }
        cp_commit();
    }

    for (int ch = 0; ch < 16; ch++) {
        asm volatile("cp.async.wait_group 2;");
        __syncthreads();
        float* sA = ring + (ch % 3) * STAGE_FLOATS;
        float* sB = sA + 128 * LDA;
        const int kc = ch * 32;
#pragma unroll
        for (int u = 0; u < 4; u++) {
            int r = ra + 32 * u;
            float4 v = *(const float4*)(sA + r * LDA + fa * 4);
            *(float4*)(out_mem + (size_t)(row0 + r) * DIM + kc + fa * 4) = v;
            sq[u] = fmaf(v.x, v.x, fmaf(v.y, v.y, fmaf(v.z, v.z, fmaf(v.w, v.w, sq[u]))));
        }
#pragma unroll
        for (int ks = 0; ks < 4; ks++) {
            const int k0 = ks * 8;
            wmma::fragment<wmma::matrix_a, 16, 16, 8, wmma::precision::tf32, wmma::row_major> af[2];
#pragma unroll
            for (int i = 0; i < 2; i++)
                wmma::load_matrix_sync(af[i], sA + (wr * 32 + i * 16) * LDA + k0, LDA);
#pragma unroll
            for (int j = 0; j < 3; j++) {
                wmma::fragment<wmma::matrix_b, 16, 16, 8, wmma::precision::tf32, wmma::col_major> bf;
                wmma::load_matrix_sync(bf, sB + (wc * 48 + j * 16) * LDB + k0, LDB);
#pragma unroll
                for (int i = 0; i < 2; i++)
                    wmma::mma_sync(acc[i][j], af[i], bf, acc[i][j]);
            }
        }
        __syncthreads();
        if (ch + 3 < 16) {
            const int kn = (ch + 3) * 32;
            uint32_t base = ring_sm + (ch % 3) * (STAGE_FLOATS * 4);
#pragma unroll
            for (int u = 0; u < 4; u++) {
                int r = ra + 32 * u;
                cp16(base + (uint32_t)((r * LDA + fa * 4) * 4),
                     mem + (size_t)(row0 + r) * DIM + kn + fa * 4);
            }
#pragma unroll
            for (int u = 0; u < 3; u++) {
                int idx = t + 256 * u;
                int r = idx >> 3, f = idx & 7;
                cp16(base + (uint32_t)((128 * LDA + r * LDB + f * 4) * 4),
                     g_B + (size_t)r * DIM + kn + f * 4);
            }
        }
        cp_commit();
    }
    asm volatile("cp.async.wait_group 0;");

#pragma unroll
    for (int u = 0; u < 4; u++) {
        float v = sq[u];
        v += __shfl_xor_sync(0xFFFFFFFFu, v, 1);
        v += __shfl_xor_sync(0xFFFFFFFFu, v, 2);
        v += __shfl_xor_sync(0xFFFFFFFFu, v, 4);
        if ((t & 7) == 0) {
            int r = (t >> 3) + 32 * u;
            float n = sqrtf(v);
            nsh[r] = n;
            g_norms[row0 + r] = n;
        }
    }
    __syncthreads();

    if (t < 128) {
        int s = row0 + t;
        float nrm = nsh[t];
        shi[t] = (nrm > 0.5f) ? 1 : 0;
        float amax = __uint_as_float(g_s.age_max_bits);
        float age = fmaxf(g_s.stepf - at[s], 0.f);
        float es = age / (amax + 1e-6f) + (1.0f - sigf(nrm));
        shv[t] = ((unsigned long long)fenc(es) << 32) | (unsigned long long)(0xFFFFFFFFu - (unsigned)s);
    }
    __syncthreads();
    for (int off = 64; off > 0; off >>= 1) {
        if (t < off) {
            shi[t] += shi[t + off];
            if (shv[t + off] > shv[t]) shv[t] = shv[t + off];
        }
        __syncthreads();
    }
    if (t == 0) {
        atomicAdd(&g_s.n_active, shi[0]);
        atomicMax(&g_s.victim_pack, shv[0]);
    }
    __syncthreads();

    float* sD = ring;
#pragma unroll
    for (int i = 0; i < 2; i++)
#pragma unroll
        for (int j = 0; j < 3; j++)
            wmma::store_matrix_sync(sD + (wr * 32 + i * 16) * LDD + wc * 48 + j * 16,
                                    acc[i][j], LDD, wmma::mem_row_major);
    __syncthreads();
    if (wid < 4) {
        int r = wid * 32 + lid;
        int s = row0 + r;
        float inv = 1.0f / fmaxf(nsh[r], 1e-12f);
#pragma unroll
        for (int c4 = 0; c4 < 16; c4++) {
            float4 v4 = *(const float4*)(sD + r * LDD + c4 * 4);
            float vv[4] = {v4.x * inv, v4.y * inv, v4.z * inv, v4.w * inv};
#pragma unroll
            for (int j = 0; j < 4; j++) {
                int c = c4 * 4 + j;
                g_sims[(size_t)c * S_SLOTS + s] = vv[j];
                float m = vv[j];
#pragma unroll
                for (int off = 16; off >= 1; off >>= 1)
                    m = fmaxf(m, __shfl_xor_sync(0xFFFFFFFFu, m, off));
                if (lid == 0) atomicMax(&g_bmax[c], fenc(m));
            }
        }
        float* cb = g_confdot + (size_t)s * 32;
#pragma unroll
        for (int q = 0; q < 8; q++) {
            float4 v = *(const float4*)(sD + r * LDD + 64 + q * 4);
            *(float4*)(cb + q * 4) = v;
        }
    }

    if (t == 0) {
        __threadfence();
        sLast = (atomicAdd(&g_cnt_main, 1u) == (unsigned)(gridDim.x - 1));
    }
    __syncthreads();
    if (sLast) {
        __shared__ float redf[64];
        if (t < 64) {
            float nov = (1.0f - fdec(g_bmax[t])) * 0.5f;
            out_nov[t] = nov;
            redf[t] = nov;
        }
        __syncthreads();
        for (int off = 32; off > 0; off >>= 1) {
            if (t < off) redf[t] += redf[t + off];
            __syncthreads();
        }
        if (t == 0) {
            g_s.nov_mean = redf[0] / (float)BATCH;
            float cap = (float)g_s.n_active / (float)S_SLOTS;
            g_s.do_erase = (cap > 0.85f) ? 1 : 0;
            float dyn = (cap < 0.3f) ? 0.08f : ((cap < 0.6f) ? 0.08f + (cap - 0.3f) * 0.733f
                                                             : 0.3f + (cap - 0.6f));
            g_s.dyn_thr = fminf(fmaxf(dyn, 0.0f), 0.7f);
            g_s.topk_thr = (cap < 0.3f) ? 0.1f : ((cap < 0.6f) ? 0.2f : 0.4f);
            g_s.raw_thr = (cap < 0.3f) ? 0.3f : 0.5f;
            g_s.victim = (int)(0xFFFFFFFFu - (unsigned)(g_s.victim_pack & 0xFFFFFFFFull));
        }
    }
}

// ---------------- 4: erase + scan + merge (ncu capture slot) ----------------
__global__ void k_scan_er(const float* __restrict__ at,
                          const float* __restrict__ el_w, const float* __restrict__ el_b,
                          const float* __restrict__ ec_b,
                          const float* __restrict__ eg_w, const float* __restrict__ eg_b) {
    int bx = blockIdx.x, t = threadIdx.x;   // 256 blocks x 256 threads
    int de = g_s.do_erase, vic = g_s.victim;
    __shared__ bool sLast;

    {
        __shared__ unsigned shm[256];
        __shared__ unsigned long long pm[256];
        __shared__ unsigned long long pa[256];
        int s = bx * 256 + t;
        float atv = at[s];
        bool zv = (de && s == vic);
        if (zv) atv = -99999.0f;
        float x = (g_s.stepf - atv) * 0.001f;
        float acc = eg_b[0];
        const float4* cd4 = (const float4*)(g_confdot + (size_t)s * 32);
#pragma unroll
        for (int jq = 0; jq < 8; jq++) {
            float4 cd = cd4[jq];
            float cda[4] = {cd.x, cd.y, cd.z, cd.w};
#pragma unroll
            for (int r = 0; r < 4; r++) {
                int j = jq * 4 + r;
                float lru = fmaxf(fmaf(x, el_w[j], el_b[j]), 0.f);
                float c = zv ? 0.f : cda[r];
                float conf = sigf(c + ec_b[j]);
                acc += lru * eg_w[j] + conf * eg_w[32 + j];
            }
        }
        float e = sigf(acc);
        g_erase[s] = e;
        float sa = g_s.stepf - atv;
        g_slotage[s] = sa;
        bool recent = (atv >= 0.f) && (sa < 3.f);
        float mp = recent ? 0.f : e;
        g_maskedpre[s] = mp;
        unsigned idxe = 0xFFFFFFFFu - (unsigned)s;
        shm[t] = __float_as_uint(mp);
        pm[t] = ((unsigned long long)fenc(mp) << 32) | (unsigned long long)idxe;
        pa[t] = ((unsigned long long)fenc(sa) << 32) | (unsigned long long)idxe;
        __syncthreads();
        for (int off = 128; off > 0; off >>= 1) {
            if (t < off) {
                if (shm[t + off] > shm[t]) shm[t] = shm[t + off];
                if (pm[t + off] > pm[t]) pm[t] = pm[t + off];
                if (pa[t + off] > pa[t]) pa[t] = pa[t + off];
            }
            __syncthreads();
        }
        if (t == 0) {
            atomicMax(&g_s.masked_max_bits, shm[0]);
            atomicMax(&g_s.wpack_m, pm[0]);
            atomicMax(&g_s.wpack_a, pa[0]);
        }
        __syncthreads();
    }

    {
        int b = bx >> 2, qt = bx & 3;
        int base = qt * 16384;
        float nm = g_s.nov_mean;
        float v0 = -FLT_MAX, v1 = -FLT_MAX, v2 = -FLT_MAX;
        int i0 = 0x7FFFFFFF, i1 = 0x7FFFFFFF, i2 = 0x7FFFFFFF;
        int cnt = 0;
        const float* row = g_sims + (size_t)b * S_SLOTS;
        for (int s = base + t; s < base + 16384; s += 256) {
            float vraw = row[s];
            if ((nm > 1.0f - vraw) && (g_norms[s] > 0.5f)) cnt++;
            float v = (de && s == vic) ? 0.f : vraw;
            if (better(v, s, v2, i2)) {
                if (better(v, s, v1, i1)) {
                    if (better(v, s, v0, i0)) { v2=v1;i2=i1; v1=v0;i1=i0; v0=v;i0=s; }
                    else                      { v2=v1;i2=i1; v1=v; i1=s; }
                } else                        { v2=v; i2=s; }
            }
        }
        __shared__ float sv[256 * 3];
        __shared__ int   si[256 * 3];
        __shared__ float mv[96];
        __shared__ int   mi[96];
        __shared__ int   sc[256];
        sv[t*3+0]=v0; sv[t*3+1]=v1; sv[t*3+2]=v2;
        si[t*3+0]=i0; si[t*3+1]=i1; si[t*3+2]=i2;
        sc[t] = cnt;
        __syncthreads();
        for (int off = 128; off > 0; off >>= 1) { if (t < off) sc[t] += sc[t + off]; __syncthreads(); }
        if (t < 32) {
            float w0=-FLT_MAX,w1=-FLT_MAX,w2=-FLT_MAX;
            int j0=0x7FFFFFFF,j1=0x7FFFFFFF,j2=0x7FFFFFFF;
            for (int e = t * 24; e < t * 24 + 24; e++) {
                float v = sv[e]; int s = si[e];
                if (better(v, s, w2, j2)) {
                    if (better(v, s, w1, j1)) {
                        if (better(v, s, w0, j0)) { w2=w1;j2=j1; w1=w0;j1=j0; w0=v;j0=s; }
                        else                      { w2=w1;j2=j1; w1=v; j1=s; }
                    } else                        { w2=v; j2=s; }
                }
            }
            mv[t*3+0]=w0; mv[t*3+1]=w1; mv[t*3+2]=w2;
            mi[t*3+0]=j0; mi[t*3+1]=j1; mi[t*3+2]=j2;
        }
        __syncthreads();
        if (t == 0) {
            atomicAdd(&g_s.cond_count, sc[0]);
            float w0=-FLT_MAX,w1=-FLT_MAX,w2=-FLT_MAX; int j0=0x7FFFFFFF,j1=0x7FFFFFFF,j2=0x7FFFFFFF;
            for (int e = 0; e < 96; e++) {
                float v = mv[e]; int s = mi[e];
                if (better(v, s, w2, j2)) {
                    if (better(v, s, w1, j1)) {
                        if (better(v, s, w0, j0)) { w2=w1;j2=j1; w1=w0;j1=j0; w0=v;j0=s; }
                        else                      { w2=w1;j2=j1; w1=v; j1=s; }
                    } else                        { w2=v; j2=s; }
                }
            }
            int o = (b * 4 + qt) * 3;
            g_p3v[o+0]=w0; g_p3v[o+1]=w1; g_p3v[o+2]=w2;
            g_p3i[o+0]=j0; g_p3i[o+1]=j1; g_p3i[o+2]=j2;
        }
    }

    if (t == 0) {
        __threadfence();
        sLast = (atomicAdd(&g_cnt_scan, 1u) == (unsigned)(gridDim.x - 1));
    }
    __syncthreads();
    if (sLast && t < 64) {
        int b = t;
        float w0=-FLT_MAX,w1=-FLT_MAX,w2=-FLT_MAX;
        int j0=0x7FFFFFFF,j1=0x7FFFFFFF,j2=0x7FFFFFFF;
        for (int e = 0; e < 12; e++) {
            float v = g_p3v[b*12+e]; int s = g_p3i[b*12+e];
            if (better(v, s, w2, j2)) {
                if (better(v, s, w1, j1)) {
                    if (better(v, s, w0, j0)) { w2=w1;j2=j1; w1=w0;j1=j0; w0=v;j0=s; }
                    else                      { w2=w1;j2=j1; w1=v; j1=s; }
                } else                        { w2=v; j2=s; }
            }
        }
        g_tv[b*3+0]=w0; g_tv[b*3+1]=w1; g_tv[b*3+2]=w2;
        g_ti[b*3+0]=j0; g_ti[b*3+1]=j1; g_ti[b*3+2]=j2;
    }
}

// ---------------- 5: pair MLPs (2 pairs/block, 192 blocks) + last-block finalize ----------------
__global__ void k_pair(const float* __restrict__ nc, const float* __restrict__ mem,
                       const float* __restrict__ dd_w1, const float* __restrict__ dd_b1,
                       const float* __restrict__ dd_w2, const float* __restrict__ dd_b2,
                       const float* __restrict__ ds_w1, const float* __restrict__ ds_b1,
                       const float* __restrict__ ds_w2, const float* __restrict__ ds_b2,
                       float* __restrict__ out_mem) {
    __shared__ float pr[2][1024];
    __shared__ float2 part[4][2][2][64];
    __shared__ float red[256];
    __shared__ bool sLast;
    int t = threadIdx.x;   // 256
    int pg = blockIdx.x >> 1, ch = blockIdx.x & 1;
    int p0 = pg * 2;
    int de = g_s.do_erase, vic = g_s.victim;
    for (int p = 0; p < 2; p++) {
        int pi = p0 + p;
        int b = pi / 3;
        int ti = g_ti[pi];
        bool z = (de && ti == vic);
        for (int i = t; i < 512; i += 256) {
            pr[p][i] = nc[b * 512 + i];
            pr[p][512 + i] = z ? 0.f : mem[(size_t)ti * 512 + i];
        }
    }
    __syncthreads();
    int ks = t >> 6, cg = t & 63;
    int colG = ch * 128 + 2 * cg;
    unsigned long long aD[2] = {0ull, 0ull};
    unsigned long long aS[2] = {0ull, 0ull};
    const float* dp = dd_w1 + colG;
    const float* sp = ds_w1 + colG;
    for (int k = ks * 256; k < ks * 256 + 256; k++) {
        unsigned long long wd = *(const unsigned long long*)(dp + (size_t)k * 256);
        unsigned long long ws = *(const unsigned long long*)(sp + (size_t)k * 256);
#pragma unroll
        for (int p = 0; p < 2; p++) {
            float x = pr[p][k];
            unsigned xi = __float_as_uint(x);
            unsigned long long x2;
            asm("mov.b64 %0, {%1, %2};" : "=l"(x2) : "r"(xi), "r"(xi));
            asm("fma.rn.f32x2 %0, %1, %2, %0;" : "+l"(aD[p]) : "l"(x2), "l"(wd));
            asm("fma.rn.f32x2 %0, %1, %2, %0;" : "+l"(aS[p]) : "l"(x2), "l"(ws));
        }
    }
#pragma unroll
    for (int p = 0; p < 2; p++) {
        part[ks][p][0][cg] = *reinterpret_cast<float2*>(&aD[p]);
        part[ks][p][1][cg] = *reinterpret_cast<float2*>(&aS[p]);
    }
    __syncthreads();
    float vals[4];
    if (t < 128) {
        int c = t;
        int cG = ch * 128 + c;
#pragma unroll
        for (int p = 0; p < 2; p++) {
#pragma unroll
            for (int net = 0; net < 2; net++) {
                float s = 0.f;
#pragma unroll
                for (int kq = 0; kq < 4; kq++) {
                    float2 f2 = part[kq][p][net][c >> 1];
                    s += (c & 1) ? f2.y : f2.x;
                }
                s += net ? ds_b1[cG] : dd_b1[cG];
                s = fmaxf(s, 0.f) * (net ? ds_w2[cG] : dd_w2[cG]);
                vals[p * 2 + net] = s;
            }
        }
    }
    for (int pn = 0; pn < 4; pn++) {
        __syncthreads();
        red[t] = (t < 128) ? vals[pn] : 0.f;
        __syncthreads();
        for (int off = 128; off > 0; off >>= 1) { if (t < off) red[t] += red[t + off]; __syncthreads(); }
        if (t == 0) atomicAdd(&g_pairacc[(p0 + (pn >> 1)) * 2 + (pn & 1)], red[0]);
    }

    if (t == 0) {
        __threadfence();
        sLast = (atomicAdd(&g_cnt_pair, 1u) == (unsigned)(gridDim.x - 1));
    }
    __syncthreads();
    if (sLast) {
        if (t < BATCH * 3) {
            float prob = sigf(g_pairacc[t * 2 + 0] + dd_b2[0]);
            float st   = sigf(g_pairacc[t * 2 + 1] + ds_b2[0]);
            g_strength[t] = st;
            float tv = g_tv[t];
            g_apply[t] = (tv > 0.7f && tv < 0.99f && prob > 0.5f) ? 1 : 0;
        }
        __syncthreads();
        if (t == 0) {
            float ssum = 0.f;
            for (int b = 0; b < BATCH; b++) ssum += g_storev[b];
            float smean = ssum / (float)BATCH;
            int na = g_s.n_active;
            int nam = na > 1 ? na : 1;
            float perc = (na > 0) ? ((float)g_s.cond_count / (64.0f * (float)nam)) : 1.0f;
            bool base = smean > g_s.raw_thr;
            bool novok = g_s.nov_mean > g_s.dyn_thr;
            bool topok = perc > g_s.topk_thr;
            bool ss = base && novok && topok;
            if (de && !novok) ss = false;
            g_s.should_store = ss ? 1 : 0;
            int usa = (__uint_as_float(g_s.masked_max_bits) <= 0.0f) ? 1 : 0;
            g_s.use_slotage = usa;
            unsigned long long wp = usa ? g_s.wpack_a : g_s.wpack_m;
            int wmax = (int)(0xFFFFFFFFu - (unsigned)(wp & 0xFFFFFFFFull));
            int wi = de ? vic : wmax;
            g_s.write_idx = wi;
            int n = 0;
            if (de) g_chg[n++] = vic;
            for (int p = 0; p < BATCH * 3; p++) {
                if (g_apply[p]) {
                    int r = g_ti[p];
                    int found = 0;
                    for (int j = 0; j < n; j++) if (g_chg[j] == r) { found = 1; break; }
                    if (!found) g_chg[n++] = r;
                }
            }
            if (ss) {
                int r = wi, found = 0;
                for (int j = 0; j < n; j++) if (g_chg[j] == r) { found = 1; break; }
                if (!found) g_chg[n++] = r;
            }
            g_nchg = n;
        }
        __syncthreads();
        for (int dd = 0; dd < 2; dd++) {
            int d = t + 256 * dd;
            float nc0 = nc[d];
            float v = nc0;
            for (int k = 0; k < 3; k++) {
                if (g_apply[k]) {
                    int r = g_ti[k];
                    float g = (de && r == vic) ? 0.f : mem[(size_t)r * 512 + d];
                    float st = g_strength[k];
                    float avg = 0.5f * (nc0 + g);
                    v = (1.f - st) * nc0 + st * avg;
                }
            }
            g_drifted0[d] = v;
            if (de) out_mem[(size_t)vic * 512 + d] = 0.f;
            for (int k = 0; k < 3; k++) {
                for (int b = 0; b < BATCH; b++) {
                    int p = b * 3 + k;
                    if (g_apply[p]) {
                        int r = g_ti[p];
                        float g = (de && r == vic) ? 0.f : mem[(size_t)r * 512 + d];
                        float st = g_strength[p];
                        float ncv = nc[b * 512 + d];
                        float avg = 0.5f * (ncv + g);
                        out_mem[(size_t)r * 512 + d] = (1.f - st) * g + st * avg;
                    }
                }
            }
            if (g_s.should_store) out_mem[(size_t)g_s.write_idx * 512 + d] = g_drifted0[d];
        }
    }
}

// ---------------- 6: outputs + rc ----------------
__global__ void k_out_rc(const float* __restrict__ at, const float* __restrict__ mem,
                         const float* __restrict__ out_mem,
                         float* __restrict__ out_at, float* __restrict__ out_erase,
                         float* __restrict__ out_rc) {
    int bx = blockIdx.x, t = threadIdx.x;
    int s = bx * 256 + t;
    float atv = at[s];
    if (g_s.do_erase && s == g_s.victim) atv = -99999.0f;
    if (g_s.should_store && s == g_s.write_idx) atv = g_s.stepf;
    out_at[s] = atv;
    float mf = g_s.use_slotage ? g_slotage[s] : g_maskedpre[s];
    out_erase[s] = (g_s.should_store && !g_s.do_erase) ? mf : g_erase[s];
    if (bx == 0) {
        __shared__ float sh[256];
        int n = g_nchg;
        float acc = 0.f;
        for (int j = t; j < n * 512; j += 256) {
            int r = g_chg[j >> 9];
            int d = j & 511;
            acc += fabsf(out_mem[(size_t)r * 512 + d] - mem[(size_t)r * 512 + d]);
        }
        sh[t] = acc; __syncthreads();
        for (int off = 128; off > 0; off >>= 1) { if (t < off) sh[t] += sh[t + off]; __syncthreads(); }
        if (t == 0) out_rc[0] = sh[0] / ((float)S_SLOTS * (float)DIM);
    }
}

// ---------------- launch ----------------
extern "C" void kernel_launch(void* const* d_in, const int* in_sizes, int n_in,
                              void* d_out, int out_size) {
    bool dictOrder = (in_sizes[4] == 1);
    const float* nc   = (const float*)d_in[0];
    const float* q    = (const float*)d_in[1];
    const float* mem  = (const float*)d_in[2];
    const float* at   = (const float*)d_in[3];
    int base = dictOrder ? 5 : 4;
    const float* sr_w1 = (const float*)d_in[base + 0];
    const float* sr_b1 = (const float*)d_in[base + 1];
    const float* sr_g  = (const float*)d_in[base + 2];
    const float* sr_be = (const float*)d_in[base + 3];
    const float* sr_w2 = (const float*)d_in[base + 4];
    const float* sr_b2 = (const float*)d_in[base + 5];
    const float* sn_w  = (const float*)d_in[base + 6];
    const float* sn_b  = (const float*)d_in[base + 7];
    const float* sg_w  = (const float*)d_in[base + 8];
    const float* sg_b  = (const float*)d_in[base + 9];
    const float* el_w  = (const float*)d_in[base + 10];
    const float* el_b  = (const float*)d_in[base + 11];
    const float* ec_w  = (const float*)d_in[base + 12];
    const float* ec_b  = (const float*)d_in[base + 13];
    const float* eg_w  = (const float*)d_in[base + 14];
    const float* eg_b  = (const float*)d_in[base + 15];
    const float* dd_w1 = (const float*)d_in[base + 16];
    const float* dd_b1 = (const float*)d_in[base + 17];
    const float* dd_w2 = (const float*)d_in[base + 18];
    const float* dd_b2 = (const float*)d_in[base + 19];
    const float* ds_w1 = (const float*)d_in[base + 20];
    const float* ds_b1 = (const float*)d_in[base + 21];
    const float* ds_w2 = (const float*)d_in[base + 22];
    const float* ds_b2 = (const float*)d_in[base + 23];
    const void*  step  = dictOrder ? d_in[4] : d_in[28];

    float* out_mem   = (float*)d_out;
    float* out_at    = out_mem + (size_t)S_SLOTS * DIM;
    float* out_erase = out_at + S_SLOTS;
    float* out_store = out_erase + S_SLOTS;
    float* out_nov   = out_store + BATCH;
    float* out_rc    = out_nov + BATCH;

    cudaFuncSetAttribute(k_main, cudaFuncAttributeMaxDynamicSharedMemorySize, RING_BYTES);

    k_reset<<<1, 384>>>(step);                                      // 1
    k_setup<<<160 + S_SLOTS / 256, 256>>>(nc, q, at, ec_w,          // 2
                                          sr_w1, sr_b1, sr_g, sr_be, sr_w2, sr_b2,
                                          sn_w, sn_b, sg_w, sg_b, out_store);
    k_main<<<S_SLOTS / 128, 256, RING_BYTES>>>(mem, at, out_mem, out_nov); // 3
    k_scan_er<<<S_SLOTS / 256, 256>>>(at, el_w, el_b, ec_b, eg_w, eg_b);   // 4 <- ncu slot
    k_pair<<<192, 256>>>(nc, mem, dd_w1, dd_b1, dd_w2, dd_b2,       // 5
                         ds_w1, ds_b1, ds_w2, ds_b2, out_mem);
    k_out_rc<<<S_SLOTS / 256, 256>>>(at, mem, out_mem, out_at, out_erase, out_rc); // 6
}

// round 14
// speedup vs baseline: 1.0452x; 1.0452x over previous
#include <cuda_runtime.h>
#include <math.h>
#include <float.h>
#include <stdint.h>
#include <mma.h>

using namespace nvcuda;

#define S_SLOTS 65536
#define DIM     512
#define BATCH   64

#define LDA  36
#define LDB  36
#define LDD  100
#define STAGE_FLOATS ((128 + 96) * 36)
#define RING_FLOATS  (3 * STAGE_FLOATS)
#define RING_BYTES   (RING_FLOATS * 4)

// ---------------- device scratch ----------------
__device__ float g_ncinv[BATCH];
__device__ float g_B[96 * DIM];
__device__ float g_sims[(size_t)BATCH * S_SLOTS];
__device__ float g_confdot[(size_t)32 * S_SLOTS];    // TRANSPOSED: [c][s]
__device__ float g_norms[S_SLOTS];
__device__ float g_erase[S_SLOTS];
__device__ float g_maskedpre[S_SLOTS];
__device__ float g_slotage[S_SLOTS];
__device__ unsigned g_bmax[BATCH];
__device__ float g_storev[BATCH];
__device__ int   g_ti[BATCH * 3];
__device__ float g_tv[BATCH * 3];
__device__ float g_p3v[BATCH * 8 * 3];
__device__ int   g_p3i[BATCH * 8 * 3];
__device__ float g_pairacc[BATCH * 3 * 2];
__device__ float g_strength[BATCH * 3];
__device__ int   g_apply[BATCH * 3];
__device__ float g_drifted0[DIM];
__device__ int   g_chg[256];
__device__ int   g_nchg;
__device__ unsigned g_cnt_main, g_cnt_scan, g_cnt_pair;

struct Scalars {
    float stepf;
    int   n_active;
    unsigned int age_max_bits;
    unsigned long long victim_pack;
    int   cond_count;
    unsigned int masked_max_bits;
    unsigned long long wpack_m;
    unsigned long long wpack_a;
    int   do_erase;
    int   victim;
    float dyn_thr, topk_thr, raw_thr;
    float nov_mean;
    int   should_store;
    int   use_slotage;
    int   write_idx;
};
__device__ Scalars g_s;

__device__ __forceinline__ float sigf(float x) { return 1.0f / (1.0f + __expf(-x)); }
__device__ __forceinline__ unsigned fenc(float f) {
    unsigned u = __float_as_uint(f);
    return (u & 0x80000000u) ? ~u : (u | 0x80000000u);
}
__device__ __forceinline__ float fdec(unsigned u) {
    return (u & 0x80000000u) ? __uint_as_float(u ^ 0x80000000u) : __uint_as_float(~u);
}
__device__ __forceinline__ bool better(float av, int ai, float bv, int bi) {
    return (av > bv) || (av == bv && ai < bi);
}
__device__ __forceinline__ void cp16(uint32_t dst_smem, const void* src) {
    asm volatile("cp.async.ca.shared.global [%0], [%1], 16;" :: "r"(dst_smem), "l"(src));
}
__device__ __forceinline__ void cp_commit() {
    asm volatile("cp.async.commit_group;");
}

// ---------------- 1: reset ----------------
__global__ void k_reset(const void* step_ptr) {
    int t = threadIdx.x;   // 384
    if (t == 0) {
        int   iv = *(const int*)step_ptr;
        float fv = *(const float*)step_ptr;
        g_s.stepf = (iv > 0 && iv < 100000000) ? (float)iv : fv;
        g_s.n_active = 0;
        g_s.age_max_bits = 0u;
        g_s.victim_pack = 0ull;
        g_s.cond_count = 0;
        g_s.masked_max_bits = 0u;
        g_s.wpack_m = 0ull;
        g_s.wpack_a = 0ull;
        g_cnt_main = 0u; g_cnt_scan = 0u; g_cnt_pair = 0u;
    }
    if (t < BATCH) g_bmax[t] = 0u;
    if (t < BATCH * 3 * 2) g_pairacc[t] = 0.f;
}

// ---------------- 2: norm_a + agemax ----------------
__global__ void k_na_am(const float* __restrict__ nc, const float* __restrict__ at) {
    int bx = blockIdx.x, t = threadIdx.x;   // 256 threads
    if (bx < 64) {
        __shared__ float red[256];
        float v0 = nc[bx * 512 + t];
        float v1 = nc[bx * 512 + 256 + t];
        red[t] = v0 * v0 + v1 * v1;
        __syncthreads();
        for (int off = 128; off > 0; off >>= 1) { if (t < off) red[t] += red[t + off]; __syncthreads(); }
        if (t == 0) g_ncinv[bx] = 1.0f / fmaxf(sqrtf(red[0]), 1e-12f);
    } else {
        __shared__ unsigned sh[256];
        int s = (bx - 64) * 256 + t;
        float age = fmaxf(g_s.stepf - at[s], 0.f);
        sh[t] = __float_as_uint(age);
        __syncthreads();
        for (int off = 128; off > 0; off >>= 1) {
            if (t < off && sh[t + off] > sh[t]) sh[t] = sh[t + off];
            __syncthreads();
        }
        if (t == 0) atomicMax(&g_s.age_max_bits, sh[0]);
    }
}

// ---------------- 3: prepB + store gate ----------------
__global__ void k_prep_store(const float* __restrict__ nc, const float* __restrict__ q,
                             const float* __restrict__ ec_w,
                             const float* __restrict__ sr_w1, const float* __restrict__ sr_b1,
                             const float* __restrict__ sr_g,  const float* __restrict__ sr_beta,
                             const float* __restrict__ sr_w2, const float* __restrict__ sr_b2,
                             const float* __restrict__ sn_w,  const float* __restrict__ sn_b,
                             const float* __restrict__ sg_w,  const float* __restrict__ sg_b,
                             float* __restrict__ out_store) {
    int bx = blockIdx.x, t = threadIdx.x;   // 256 threads
    if (bx < 96) {
        int r = bx;
        if (r < 64) {
            float inv = g_ncinv[r];
            for (int k = t; k < DIM; k += 256)
                g_B[r * DIM + k] = wmma::__float_to_tf32(nc[r * DIM + k] * inv);
        } else {
            int j = r - 64;
            for (int k = t; k < DIM; k += 256)
                g_B[r * DIM + k] = wmma::__float_to_tf32(ec_w[(size_t)k * 32 + j]);
        }
        return;
    }
    int b = bx - 96;
    __shared__ float comb[1024];
    __shared__ float hpart[4][256];
    __shared__ float rh[256];
    __shared__ float red[256];
    __shared__ float r2part[2][128];
    __shared__ float nfpart[2][128];
    for (int i = t; i < 512; i += 256) {
        comb[i] = nc[b * 512 + i];
        comb[512 + i] = q[b * 512 + i];
    }
    __syncthreads();
    int ks = t >> 6, cg = t & 63;
    {
        float4 a = make_float4(0.f, 0.f, 0.f, 0.f);
        const float* wp = sr_w1 + 4 * cg;
        for (int k = ks * 256; k < ks * 256 + 256; k++) {
            float4 w = *(const float4*)(wp + (size_t)k * 256);
            float x = comb[k];
            a.x = fmaf(x, w.x, a.x); a.y = fmaf(x, w.y, a.y);
            a.z = fmaf(x, w.z, a.z); a.w = fmaf(x, w.w, a.w);
        }
        ((float4*)&hpart[ks][0])[cg] = a;
    }
    __syncthreads();
    float h = hpart[0][t] + hpart[1][t] + hpart[2][t] + hpart[3][t] + sr_b1[t];
    red[t] = h; __syncthreads();
    for (int off = 128; off > 0; off >>= 1) { if (t < off) red[t] += red[t + off]; __syncthreads(); }
    float m = red[0] / 256.0f; __syncthreads();
    float d = h - m;
    red[t] = d * d; __syncthreads();
    for (int off = 128; off > 0; off >>= 1) { if (t < off) red[t] += red[t + off]; __syncthreads(); }
    float var = red[0] / 256.0f; __syncthreads();
    float hn = d * rsqrtf(var + 1e-5f) * sr_g[t] + sr_beta[t];
    rh[t] = fmaxf(hn, 0.f);
    __syncthreads();
    {
        int ks2 = t >> 7, c = t & 127;
        float a = 0.f;
        for (int k = ks2 * 128; k < ks2 * 128 + 128; k++)
            a = fmaf(rh[k], sr_w2[(size_t)k * 128 + c], a);
        r2part[ks2][c] = a;
    }
    {
        int ks2 = t >> 7, c = t & 127;
        float a = 0.f;
        for (int k = ks2 * 256; k < ks2 * 256 + 256; k++)
            a = fmaf(comb[k], sn_w[(size_t)k * 128 + c], a);
        nfpart[ks2][c] = a;
    }
    __syncthreads();
    float val = 0.f;
    if (t < 128) {
        float r = fmaxf(r2part[0][t] + r2part[1][t] + sr_b2[t], 0.f);
        float nf = sigf(nfpart[0][t] + nfpart[1][t] + sn_b[t]);
        val = (r + nf) * sg_w[t];
    }
    red[t] = val; __syncthreads();
    for (int off = 128; off > 0; off >>= 1) { if (t < off) red[t] += red[t + off]; __syncthreads(); }
    if (t == 0) {
        float sc = sigf(red[0] + sg_b[0]);
        g_storev[b] = sc;
        out_store[b] = sc;
    }
}

// ---------------- 4: wmma tf32 GEMM (R12 k_main + transposed confdot stores) ----------------
__global__ void __launch_bounds__(256, 2) k_main(const float* __restrict__ mem,
                                                 const float* __restrict__ at,
                                                 float* __restrict__ out_mem,
                                                 float* __restrict__ out_nov) {
    extern __shared__ __align__(16) float ring[];
    __shared__ float nsh[128];
    __shared__ int shi[128];
    __shared__ unsigned long long shv[128];
    __shared__ bool sLast;

    const int t = threadIdx.x;
    const int wid = t >> 5, lid = t & 31;
    const int row0 = blockIdx.x * 128;
    const int wr = wid >> 1;
    const int wc = wid & 1;
    const int ra = t >> 3, fa = t & 7;

    uint32_t ring_sm = (uint32_t)__cvta_generic_to_shared(ring);

    wmma::fragment<wmma::accumulator, 16, 16, 8, float> acc[2][3];
#pragma unroll
    for (int i = 0; i < 2; i++)
#pragma unroll
        for (int j = 0; j < 3; j++) wmma::fill_fragment(acc[i][j], 0.0f);
    float sq[4] = {0.f, 0.f, 0.f, 0.f};

#pragma unroll
    for (int st = 0; st < 3; st++) {
        const int kc = st * 32;
        uint32_t base = ring_sm + st * (STAGE_FLOATS * 4);
#pragma unroll
        for (int u = 0; u < 4; u++) {
            int r = ra + 32 * u;
            cp16(base + (uint32_t)((r * LDA + fa * 4) * 4),
                 mem + (size_t)(row0 + r) * DIM + kc + fa * 4);
        }
#pragma unroll
        for (int u = 0; u < 3; u++) {
            int idx = t + 256 * u;
            int r = idx >> 3, f = idx & 7;
            cp16(base + (uint32_t)((128 * LDA + r * LDB + f * 4) * 4),
                 g_B + (size_t)r * DIM + kc + f * 4);
        }
        cp_commit();
    }

    for (int ch = 0; ch < 16; ch++) {
        asm volatile("cp.async.wait_group 2;");
        __syncthreads();
        float* sA = ring + (ch % 3) * STAGE_FLOATS;
        float* sB = sA + 128 * LDA;
        const int kc = ch * 32;
#pragma unroll
        for (int u = 0; u < 4; u++) {
            int r = ra + 32 * u;
            float4 v = *(const float4*)(sA + r * LDA + fa * 4);
            *(float4*)(out_mem + (size_t)(row0 + r) * DIM + kc + fa * 4) = v;
            sq[u] = fmaf(v.x, v.x, fmaf(v.y, v.y, fmaf(v.z, v.z, fmaf(v.w, v.w, sq[u]))));
        }
#pragma unroll
        for (int ks = 0; ks < 4; ks++) {
            const int k0 = ks * 8;
            wmma::fragment<wmma::matrix_a, 16, 16, 8, wmma::precision::tf32, wmma::row_major> af[2];
#pragma unroll
            for (int i = 0; i < 2; i++)
                wmma::load_matrix_sync(af[i], sA + (wr * 32 + i * 16) * LDA + k0, LDA);
#pragma unroll
            for (int j = 0; j < 3; j++) {
                wmma::fragment<wmma::matrix_b, 16, 16, 8, wmma::precision::tf32, wmma::col_major> bf;
                wmma::load_matrix_sync(bf, sB + (wc * 48 + j * 16) * LDB + k0, LDB);
#pragma unroll
                for (int i = 0; i < 2; i++)
                    wmma::mma_sync(acc[i][j], af[i], bf, acc[i][j]);
            }
        }
        __syncthreads();
        if (ch + 3 < 16) {
            const int kn = (ch + 3) * 32;
            uint32_t base = ring_sm + (ch % 3) * (STAGE_FLOATS * 4);
#pragma unroll
            for (int u = 0; u < 4; u++) {
                int r = ra + 32 * u;
                cp16(base + (uint32_t)((r * LDA + fa * 4) * 4),
                     mem + (size_t)(row0 + r) * DIM + kn + fa * 4);
            }
#pragma unroll
            for (int u = 0; u < 3; u++) {
                int idx = t + 256 * u;
                int r = idx >> 3, f = idx & 7;
                cp16(base + (uint32_t)((128 * LDA + r * LDB + f * 4) * 4),
                     g_B + (size_t)r * DIM + kn + f * 4);
            }
        }
        cp_commit();
    }
    asm volatile("cp.async.wait_group 0;");

#pragma unroll
    for (int u = 0; u < 4; u++) {
        float v = sq[u];
        v += __shfl_xor_sync(0xFFFFFFFFu, v, 1);
        v += __shfl_xor_sync(0xFFFFFFFFu, v, 2);
        v += __shfl_xor_sync(0xFFFFFFFFu, v, 4);
        if ((t & 7) == 0) {
            int r = (t >> 3) + 32 * u;
            float n = sqrtf(v);
            nsh[r] = n;
            g_norms[row0 + r] = n;
        }
    }
    __syncthreads();

    if (t < 128) {
        int s = row0 + t;
        float nrm = nsh[t];
        shi[t] = (nrm > 0.5f) ? 1 : 0;
        float amax = __uint_as_float(g_s.age_max_bits);
        float age = fmaxf(g_s.stepf - at[s], 0.f);
        float es = age / (amax + 1e-6f) + (1.0f - sigf(nrm));
        shv[t] = ((unsigned long long)fenc(es) << 32) | (unsigned long long)(0xFFFFFFFFu - (unsigned)s);
    }
    __syncthreads();
    for (int off = 64; off > 0; off >>= 1) {
        if (t < off) {
            shi[t] += shi[t + off];
            if (shv[t + off] > shv[t]) shv[t] = shv[t + off];
        }
        __syncthreads();
    }
    if (t == 0) {
        atomicAdd(&g_s.n_active, shi[0]);
        atomicMax(&g_s.victim_pack, shv[0]);
    }
    __syncthreads();

    float* sD = ring;
#pragma unroll
    for (int i = 0; i < 2; i++)
#pragma unroll
        for (int j = 0; j < 3; j++)
            wmma::store_matrix_sync(sD + (wr * 32 + i * 16) * LDD + wc * 48 + j * 16,
                                    acc[i][j], LDD, wmma::mem_row_major);
    __syncthreads();
    if (wid < 4) {
        int r = wid * 32 + lid;
        int s = row0 + r;
        float inv = 1.0f / fmaxf(nsh[r], 1e-12f);
#pragma unroll
        for (int c4 = 0; c4 < 16; c4++) {
            float4 v4 = *(const float4*)(sD + r * LDD + c4 * 4);
            float vv[4] = {v4.x * inv, v4.y * inv, v4.z * inv, v4.w * inv};
#pragma unroll
            for (int j = 0; j < 4; j++) {
                int c = c4 * 4 + j;
                g_sims[(size_t)c * S_SLOTS + s] = vv[j];
                float m = vv[j];
#pragma unroll
                for (int off = 16; off >= 1; off >>= 1)
                    m = fmaxf(m, __shfl_xor_sync(0xFFFFFFFFu, m, off));
                if (lid == 0) atomicMax(&g_bmax[c], fenc(m));
            }
        }
        // confdot transposed [c][s]: coalesced stores
#pragma unroll
        for (int c = 0; c < 32; c++)
            g_confdot[(size_t)c * S_SLOTS + s] = sD[r * LDD + 64 + c];
    }

    if (t == 0) {
        __threadfence();
        sLast = (atomicAdd(&g_cnt_main, 1u) == (unsigned)(gridDim.x - 1));
    }
    __syncthreads();
    if (sLast) {
        __shared__ float redf[64];
        if (t < 64) {
            float nov = (1.0f - fdec(g_bmax[t])) * 0.5f;
            out_nov[t] = nov;
            redf[t] = nov;
        }
        __syncthreads();
        for (int off = 32; off > 0; off >>= 1) {
            if (t < off) redf[t] += redf[t + off];
            __syncthreads();
        }
        if (t == 0) {
            g_s.nov_mean = redf[0] / (float)BATCH;
            float cap = (float)g_s.n_active / (float)S_SLOTS;
            g_s.do_erase = (cap > 0.85f) ? 1 : 0;
            float dyn = (cap < 0.3f) ? 0.08f : ((cap < 0.6f) ? 0.08f + (cap - 0.3f) * 0.733f
                                                             : 0.3f + (cap - 0.6f));
            g_s.dyn_thr = fminf(fmaxf(dyn, 0.0f), 0.7f);
            g_s.topk_thr = (cap < 0.3f) ? 0.1f : ((cap < 0.6f) ? 0.2f : 0.4f);
            g_s.raw_thr = (cap < 0.3f) ? 0.3f : 0.5f;
            g_s.victim = (int)(0xFFFFFFFFu - (unsigned)(g_s.victim_pack & 0xFFFFFFFFull));
        }
    }
}

// ---------------- 5: erase (128 slots/blk) + scan (8-way) + merge, 512 blocks ----------------
__global__ void k_scan_er(const float* __restrict__ at,
                          const float* __restrict__ el_w, const float* __restrict__ el_b,
                          const float* __restrict__ ec_b,
                          const float* __restrict__ eg_w, const float* __restrict__ eg_b) {
    int bx = blockIdx.x, t = threadIdx.x;   // 512 blocks x 256 threads
    int de = g_s.do_erase, vic = g_s.victim;
    __shared__ bool sLast;

    // ---- erase part: slots bx*128 .. +127, threads t<128 ----
    {
        __shared__ unsigned shm[128];
        __shared__ unsigned long long pm[128];
        __shared__ unsigned long long pa[128];
        if (t < 128) {
            int s = bx * 128 + t;
            float atv = at[s];
            bool zv = (de && s == vic);
            if (zv) atv = -99999.0f;
            float x = (g_s.stepf - atv) * 0.001f;
            float acc = eg_b[0];
#pragma unroll
            for (int j = 0; j < 32; j++) {
                float lru = fmaxf(fmaf(x, el_w[j], el_b[j]), 0.f);
                float c = zv ? 0.f : g_confdot[(size_t)j * S_SLOTS + s];
                float conf = sigf(c + ec_b[j]);
                acc += lru * eg_w[j] + conf * eg_w[32 + j];
            }
            float e = sigf(acc);
            g_erase[s] = e;
            float sa = g_s.stepf - atv;
            g_slotage[s] = sa;
            bool recent = (atv >= 0.f) && (sa < 3.f);
            float mp = recent ? 0.f : e;
            g_maskedpre[s] = mp;
            unsigned idxe = 0xFFFFFFFFu - (unsigned)s;
            shm[t] = __float_as_uint(mp);
            pm[t] = ((unsigned long long)fenc(mp) << 32) | (unsigned long long)idxe;
            pa[t] = ((unsigned long long)fenc(sa) << 32) | (unsigned long long)idxe;
        }
        __syncthreads();
        for (int off = 64; off > 0; off >>= 1) {
            if (t < off) {
                if (shm[t + off] > shm[t]) shm[t] = shm[t + off];
                if (pm[t + off] > pm[t]) pm[t] = pm[t + off];
                if (pa[t + off] > pa[t]) pa[t] = pa[t + off];
            }
            __syncthreads();
        }
        if (t == 0) {
            atomicMax(&g_s.masked_max_bits, shm[0]);
            atomicMax(&g_s.wpack_m, pm[0]);
            atomicMax(&g_s.wpack_a, pa[0]);
        }
        __syncthreads();
    }

    // ---- scan part: b = bx>>3, octant = bx&7 (8192 slots) ----
    {
        int b = bx >> 3, oc = bx & 7;
        int base = oc * 8192;
        float nm = g_s.nov_mean;
        float v0 = -FLT_MAX, v1 = -FLT_MAX, v2 = -FLT_MAX;
        int i0 = 0x7FFFFFFF, i1 = 0x7FFFFFFF, i2 = 0x7FFFFFFF;
        int cnt = 0;
        const float* row = g_sims + (size_t)b * S_SLOTS;
        for (int s = base + t; s < base + 8192; s += 256) {
            float vraw = row[s];
            if ((nm > 1.0f - vraw) && (g_norms[s] > 0.5f)) cnt++;
            float v = (de && s == vic) ? 0.f : vraw;
            if (better(v, s, v2, i2)) {
                if (better(v, s, v1, i1)) {
                    if (better(v, s, v0, i0)) { v2=v1;i2=i1; v1=v0;i1=i0; v0=v;i0=s; }
                    else                      { v2=v1;i2=i1; v1=v; i1=s; }
                } else                        { v2=v; i2=s; }
            }
        }
        __shared__ float sv[256 * 3];
        __shared__ int   si[256 * 3];
        __shared__ float mv[96];
        __shared__ int   mi[96];
        __shared__ int   sc[256];
        sv[t*3+0]=v0; sv[t*3+1]=v1; sv[t*3+2]=v2;
        si[t*3+0]=i0; si[t*3+1]=i1; si[t*3+2]=i2;
        sc[t] = cnt;
        __syncthreads();
        for (int off = 128; off > 0; off >>= 1) { if (t < off) sc[t] += sc[t + off]; __syncthreads(); }
        if (t < 32) {
            float w0=-FLT_MAX,w1=-FLT_MAX,w2=-FLT_MAX;
            int j0=0x7FFFFFFF,j1=0x7FFFFFFF,j2=0x7FFFFFFF;
            for (int e = t * 24; e < t * 24 + 24; e++) {
                float v = sv[e]; int s = si[e];
                if (better(v, s, w2, j2)) {
                    if (better(v, s, w1, j1)) {
                        if (better(v, s, w0, j0)) { w2=w1;j2=j1; w1=w0;j1=j0; w0=v;j0=s; }
                        else                      { w2=w1;j2=j1; w1=v; j1=s; }
                    } else                        { w2=v; j2=s; }
                }
            }
            mv[t*3+0]=w0; mv[t*3+1]=w1; mv[t*3+2]=w2;
            mi[t*3+0]=j0; mi[t*3+1]=j1; mi[t*3+2]=j2;
        }
        __syncthreads();
        if (t == 0) {
            atomicAdd(&g_s.cond_count, sc[0]);
            float w0=-FLT_MAX,w1=-FLT_MAX,w2=-FLT_MAX; int j0=0x7FFFFFFF,j1=0x7FFFFFFF,j2=0x7FFFFFFF;
            for (int e = 0; e < 96; e++) {
                float v = mv[e]; int s = mi[e];
                if (better(v, s, w2, j2)) {
                    if (better(v, s, w1, j1)) {
                        if (better(v, s, w0, j0)) { w2=w1;j2=j1; w1=w0;j1=j0; w0=v;j0=s; }
                        else                      { w2=w1;j2=j1; w1=v; j1=s; }
                    } else                        { w2=v; j2=s; }
                }
            }
            int o = (b * 8 + oc) * 3;
            g_p3v[o+0]=w0; g_p3v[o+1]=w1; g_p3v[o+2]=w2;
            g_p3i[o+0]=j0; g_p3i[o+1]=j1; g_p3i[o+2]=j2;
        }
    }

    if (t == 0) {
        __threadfence();
        sLast = (atomicAdd(&g_cnt_scan, 1u) == (unsigned)(gridDim.x - 1));
    }
    __syncthreads();
    if (sLast && t < 64) {
        int b = t;
        float w0=-FLT_MAX,w1=-FLT_MAX,w2=-FLT_MAX;
        int j0=0x7FFFFFFF,j1=0x7FFFFFFF,j2=0x7FFFFFFF;
        for (int e = 0; e < 24; e++) {
            float v = g_p3v[b*24+e]; int s = g_p3i[b*24+e];
            if (better(v, s, w2, j2)) {
                if (better(v, s, w1, j1)) {
                    if (better(v, s, w0, j0)) { w2=w1;j2=j1; w1=w0;j1=j0; w0=v;j0=s; }
                    else                      { w2=w1;j2=j1; w1=v; j1=s; }
                } else                        { w2=v; j2=s; }
            }
        }
        g_tv[b*3+0]=w0; g_tv[b*3+1]=w1; g_tv[b*3+2]=w2;
        g_ti[b*3+0]=j0; g_ti[b*3+1]=j1; g_ti[b*3+2]=j2;
    }
}

// ---------------- 6: pair MLPs (4 pairs/block, 96 blocks) + last-block finalize ----------------
__global__ void k_pair(const float* __restrict__ nc, const float* __restrict__ mem,
                       const float* __restrict__ dd_w1, const float* __restrict__ dd_b1,
                       const float* __restrict__ dd_w2, const float* __restrict__ dd_b2,
                       const float* __restrict__ ds_w1, const float* __restrict__ ds_b1,
                       const float* __restrict__ ds_w2, const float* __restrict__ ds_b2,
                       float* __restrict__ out_mem) {
    __shared__ float pr[4][1024];
    __shared__ float2 part[4][4][2][64];
    __shared__ float red[256];
    __shared__ bool sLast;
    int t = threadIdx.x;   // 256
    int pg = blockIdx.x >> 1, ch = blockIdx.x & 1;
    int p0 = pg * 4;
    int de = g_s.do_erase, vic = g_s.victim;
    for (int p = 0; p < 4; p++) {
        int pi = p0 + p;
        int b = pi / 3;
        int ti = g_ti[pi];
        bool z = (de && ti == vic);
        for (int i = t; i < 512; i += 256) {
            pr[p][i] = nc[b * 512 + i];
            pr[p][512 + i] = z ? 0.f : mem[(size_t)ti * 512 + i];
        }
    }
    __syncthreads();
    int ks = t >> 6, cg = t & 63;
    int colG = ch * 128 + 2 * cg;
    unsigned long long aD[4] = {0ull,0ull,0ull,0ull};
    unsigned long long aS[4] = {0ull,0ull,0ull,0ull};
    const float* dp = dd_w1 + colG;
    const float* sp = ds_w1 + colG;
    for (int k = ks * 256; k < ks * 256 + 256; k++) {
        unsigned long long wd = *(const unsigned long long*)(dp + (size_t)k * 256);
        unsigned long long ws = *(const unsigned long long*)(sp + (size_t)k * 256);
#pragma unroll
        for (int p = 0; p < 4; p++) {
            float x = pr[p][k];
            unsigned xi = __float_as_uint(x);
            unsigned long long x2;
            asm("mov.b64 %0, {%1, %2};" : "=l"(x2) : "r"(xi), "r"(xi));
            asm("fma.rn.f32x2 %0, %1, %2, %0;" : "+l"(aD[p]) : "l"(x2), "l"(wd));
            asm("fma.rn.f32x2 %0, %1, %2, %0;" : "+l"(aS[p]) : "l"(x2), "l"(ws));
        }
    }
#pragma unroll
    for (int p = 0; p < 4; p++) {
        part[ks][p][0][cg] = *reinterpret_cast<float2*>(&aD[p]);
        part[ks][p][1][cg] = *reinterpret_cast<float2*>(&aS[p]);
    }
    __syncthreads();
    float vals[8];
    if (t < 128) {
        int c = t;
        int cG = ch * 128 + c;
#pragma unroll
        for (int p = 0; p < 4; p++) {
#pragma unroll
            for (int net = 0; net < 2; net++) {
                float s = 0.f;
#pragma unroll
                for (int kq = 0; kq < 4; kq++) {
                    float2 f2 = part[kq][p][net][c >> 1];
                    s += (c & 1) ? f2.y : f2.x;
                }
                s += net ? ds_b1[cG] : dd_b1[cG];
                s = fmaxf(s, 0.f) * (net ? ds_w2[cG] : dd_w2[cG]);
                vals[p * 2 + net] = s;
            }
        }
    }
    for (int pn = 0; pn < 8; pn++) {
        __syncthreads();
        red[t] = (t < 128) ? vals[pn] : 0.f;
        __syncthreads();
        for (int off = 128; off > 0; off >>= 1) { if (t < off) red[t] += red[t + off]; __syncthreads(); }
        if (t == 0) atomicAdd(&g_pairacc[(p0 + (pn >> 1)) * 2 + (pn & 1)], red[0]);
    }

    if (t == 0) {
        __threadfence();
        sLast = (atomicAdd(&g_cnt_pair, 1u) == (unsigned)(gridDim.x - 1));
    }
    __syncthreads();
    if (sLast) {
        if (t < BATCH * 3) {
            float prob = sigf(g_pairacc[t * 2 + 0] + dd_b2[0]);
            float st   = sigf(g_pairacc[t * 2 + 1] + ds_b2[0]);
            g_strength[t] = st;
            float tv = g_tv[t];
            g_apply[t] = (tv > 0.7f && tv < 0.99f && prob > 0.5f) ? 1 : 0;
        }
        __syncthreads();
        if (t == 0) {
            float ssum = 0.f;
            for (int b = 0; b < BATCH; b++) ssum += g_storev[b];
            float smean = ssum / (float)BATCH;
            int na = g_s.n_active;
            int nam = na > 1 ? na : 1;
            float perc = (na > 0) ? ((float)g_s.cond_count / (64.0f * (float)nam)) : 1.0f;
            bool base = smean > g_s.raw_thr;
            bool novok = g_s.nov_mean > g_s.dyn_thr;
            bool topok = perc > g_s.topk_thr;
            bool ss = base && novok && topok;
            if (de && !novok) ss = false;
            g_s.should_store = ss ? 1 : 0;
            int usa = (__uint_as_float(g_s.masked_max_bits) <= 0.0f) ? 1 : 0;
            g_s.use_slotage = usa;
            unsigned long long wp = usa ? g_s.wpack_a : g_s.wpack_m;
            int wmax = (int)(0xFFFFFFFFu - (unsigned)(wp & 0xFFFFFFFFull));
            int wi = de ? vic : wmax;
            g_s.write_idx = wi;
            int n = 0;
            if (de) g_chg[n++] = vic;
            for (int p = 0; p < BATCH * 3; p++) {
                if (g_apply[p]) {
                    int r = g_ti[p];
                    int found = 0;
                    for (int j = 0; j < n; j++) if (g_chg[j] == r) { found = 1; break; }
                    if (!found) g_chg[n++] = r;
                }
            }
            if (ss) {
                int r = wi, found = 0;
                for (int j = 0; j < n; j++) if (g_chg[j] == r) { found = 1; break; }
                if (!found) g_chg[n++] = r;
            }
            g_nchg = n;
        }
        __syncthreads();
        for (int dd = 0; dd < 2; dd++) {
            int d = t + 256 * dd;
            float nc0 = nc[d];
            float v = nc0;
            for (int k = 0; k < 3; k++) {
                if (g_apply[k]) {
                    int r = g_ti[k];
                    float g = (de && r == vic) ? 0.f : mem[(size_t)r * 512 + d];
                    float st = g_strength[k];
                    float avg = 0.5f * (nc0 + g);
                    v = (1.f - st) * nc0 + st * avg;
                }
            }
            g_drifted0[d] = v;
            if (de) out_mem[(size_t)vic * 512 + d] = 0.f;
            for (int k = 0; k < 3; k++) {
                for (int b = 0; b < BATCH; b++) {
                    int p = b * 3 + k;
                    if (g_apply[p]) {
                        int r = g_ti[p];
                        float g = (de && r == vic) ? 0.f : mem[(size_t)r * 512 + d];
                        float st = g_strength[p];
                        float ncv = nc[b * 512 + d];
                        float avg = 0.5f * (ncv + g);
                        out_mem[(size_t)r * 512 + d] = (1.f - st) * g + st * avg;
                    }
                }
            }
            if (g_s.should_store) out_mem[(size_t)g_s.write_idx * 512 + d] = g_drifted0[d];
        }
    }
}

// ---------------- 7: outputs + rc ----------------
__global__ void k_out_rc(const float* __restrict__ at, const float* __restrict__ mem,
                         const float* __restrict__ out_mem,
                         float* __restrict__ out_at, float* __restrict__ out_erase,
                         float* __restrict__ out_rc) {
    int bx = blockIdx.x, t = threadIdx.x;
    int s = bx * 256 + t;
    float atv = at[s];
    if (g_s.do_erase && s == g_s.victim) atv = -99999.0f;
    if (g_s.should_store && s == g_s.write_idx) atv = g_s.stepf;
    out_at[s] = atv;
    float mf = g_s.use_slotage ? g_slotage[s] : g_maskedpre[s];
    out_erase[s] = (g_s.should_store && !g_s.do_erase) ? mf : g_erase[s];
    if (bx == 0) {
        __shared__ float sh[256];
        int n = g_nchg;
        float acc = 0.f;
        for (int j = t; j < n * 512; j += 256) {
            int r = g_chg[j >> 9];
            int d = j & 511;
            acc += fabsf(out_mem[(size_t)r * 512 + d] - mem[(size_t)r * 512 + d]);
        }
        sh[t] = acc; __syncthreads();
        for (int off = 128; off > 0; off >>= 1) { if (t < off) sh[t] += sh[t + off]; __syncthreads(); }
        if (t == 0) out_rc[0] = sh[0] / ((float)S_SLOTS * (float)DIM);
    }
}

// ---------------- launch ----------------
extern "C" void kernel_launch(void* const* d_in, const int* in_sizes, int n_in,
                              void* d_out, int out_size) {
    bool dictOrder = (in_sizes[4] == 1);
    const float* nc   = (const float*)d_in[0];
    const float* q    = (const float*)d_in[1];
    const float* mem  = (const float*)d_in[2];
    const float* at   = (const float*)d_in[3];
    int base = dictOrder ? 5 : 4;
    const float* sr_w1 = (const float*)d_in[base + 0];
    const float* sr_b1 = (const float*)d_in[base + 1];
    const float* sr_g  = (const float*)d_in[base + 2];
    const float* sr_be = (const float*)d_in[base + 3];
    const float* sr_w2 = (const float*)d_in[base + 4];
    const float* sr_b2 = (const float*)d_in[base + 5];
    const float* sn_w  = (const float*)d_in[base + 6];
    const float* sn_b  = (const float*)d_in[base + 7];
    const float* sg_w  = (const float*)d_in[base + 8];
    const float* sg_b  = (const float*)d_in[base + 9];
    const float* el_w  = (const float*)d_in[base + 10];
    const float* el_b  = (const float*)d_in[base + 11];
    const float* ec_w  = (const float*)d_in[base + 12];
    const float* ec_b  = (const float*)d_in[base + 13];
    const float* eg_w  = (const float*)d_in[base + 14];
    const float* eg_b  = (const float*)d_in[base + 15];
    const float* dd_w1 = (const float*)d_in[base + 16];
    const float* dd_b1 = (const float*)d_in[base + 17];
    const float* dd_w2 = (const float*)d_in[base + 18];
    const float* dd_b2 = (const float*)d_in[base + 19];
    const float* ds_w1 = (const float*)d_in[base + 20];
    const float* ds_b1 = (const float*)d_in[base + 21];
    const float* ds_w2 = (const float*)d_in[base + 22];
    const float* ds_b2 = (const float*)d_in[base + 23];
    const void*  step  = dictOrder ? d_in[4] : d_in[28];

    float* out_mem   = (float*)d_out;
    float* out_at    = out_mem + (size_t)S_SLOTS * DIM;
    float* out_erase = out_at + S_SLOTS;
    float* out_store = out_erase + S_SLOTS;
    float* out_nov   = out_store + BATCH;
    float* out_rc    = out_nov + BATCH;

    cudaFuncSetAttribute(k_main, cudaFuncAttributeMaxDynamicSharedMemorySize, RING_BYTES);

    k_reset<<<1, 384>>>(step);                                      // 1
    k_na_am<<<64 + S_SLOTS / 256, 256>>>(nc, at);                   // 2
    k_prep_store<<<160, 256>>>(nc, q, ec_w, sr_w1, sr_b1, sr_g,     // 3
                               sr_be, sr_w2, sr_b2, sn_w, sn_b, sg_w, sg_b, out_store);
    k_main<<<S_SLOTS / 128, 256, RING_BYTES>>>(mem, at, out_mem, out_nov); // 4 <- ncu slot
    k_scan_er<<<512, 256>>>(at, el_w, el_b, ec_b, eg_w, eg_b);      // 5
    k_pair<<<96, 256>>>(nc, mem, dd_w1, dd_b1, dd_w2, dd_b2,        // 6
                        ds_w1, ds_b1, ds_w2, ds_b2, out_mem);
    k_out_rc<<<S_SLOTS / 256, 256>>>(at, mem, out_mem, out_at, out_erase, out_rc); // 7
}

// round 15
// speedup vs baseline: 1.0516x; 1.0062x over previous
#include <cuda_runtime.h>
#include <math.h>
#include <float.h>
#include <stdint.h>
#include <mma.h>

using namespace nvcuda;

#define S_SLOTS 65536
#define DIM     512
#define BATCH   64

#define LDA  36
#define LDB  36
#define LDD  100
#define STAGE_FLOATS ((128 + 96) * 36)
#define RING_FLOATS  (3 * STAGE_FLOATS)
#define RING_BYTES   (RING_FLOATS * 4)

// ---------------- device scratch (zero-initialized at load; reset by k_out_rc each replay) ----------------
__device__ float g_ncinv[BATCH];
__device__ float g_B[96 * DIM];
__device__ float g_sims[(size_t)BATCH * S_SLOTS];
__device__ float g_confdot[(size_t)32 * S_SLOTS];    // [c][s]
__device__ float g_norms[S_SLOTS];
__device__ float g_erase[S_SLOTS];
__device__ float g_maskedpre[S_SLOTS];
__device__ float g_slotage[S_SLOTS];
__device__ unsigned g_bmax[BATCH];
__device__ float g_storev[BATCH];
__device__ int   g_ti[BATCH * 3];
__device__ float g_tv[BATCH * 3];
__device__ float g_p3v[BATCH * 8 * 3];
__device__ int   g_p3i[BATCH * 8 * 3];
__device__ float g_pairacc[BATCH * 3 * 2];
__device__ float g_strength[BATCH * 3];
__device__ int   g_apply[BATCH * 3];
__device__ float g_drifted0[DIM];
__device__ int   g_chg[256];
__device__ int   g_nchg;
__device__ unsigned g_cnt_main, g_cnt_scan, g_cnt_pair;

struct Scalars {
    int   n_active;
    unsigned int age_max_bits;
    unsigned long long victim_pack;
    int   cond_count;
    unsigned int masked_max_bits;
    unsigned long long wpack_m;
    unsigned long long wpack_a;
    int   do_erase;
    int   victim;
    float dyn_thr, topk_thr, raw_thr;
    float nov_mean;
    int   should_store;
    int   use_slotage;
    int   write_idx;
};
__device__ Scalars g_s;

__device__ __forceinline__ float get_stepf(const void* p) {
    int   iv = *(const int*)p;
    float fv = *(const float*)p;
    return (iv > 0 && iv < 100000000) ? (float)iv : fv;
}
__device__ __forceinline__ float sigf(float x) { return 1.0f / (1.0f + __expf(-x)); }
__device__ __forceinline__ unsigned fenc(float f) {
    unsigned u = __float_as_uint(f);
    return (u & 0x80000000u) ? ~u : (u | 0x80000000u);
}
__device__ __forceinline__ float fdec(unsigned u) {
    return (u & 0x80000000u) ? __uint_as_float(u ^ 0x80000000u) : __uint_as_float(~u);
}
__device__ __forceinline__ bool better(float av, int ai, float bv, int bi) {
    return (av > bv) || (av == bv && ai < bi);
}
__device__ __forceinline__ void cp16(uint32_t dst_smem, const void* src) {
    asm volatile("cp.async.ca.shared.global [%0], [%1], 16;" :: "r"(dst_smem), "l"(src));
}
__device__ __forceinline__ void cp_commit() {
    asm volatile("cp.async.commit_group;");
}

// ---------------- 1: norm_a + agemax ----------------
__global__ void k_na_am(const float* __restrict__ nc, const float* __restrict__ at,
                        const void* __restrict__ step_ptr) {
    int bx = blockIdx.x, t = threadIdx.x;   // 256 threads
    if (bx < 64) {
        __shared__ float red[256];
        float v0 = nc[bx * 512 + t];
        float v1 = nc[bx * 512 + 256 + t];
        red[t] = v0 * v0 + v1 * v1;
        __syncthreads();
        for (int off = 128; off > 0; off >>= 1) { if (t < off) red[t] += red[t + off]; __syncthreads(); }
        if (t == 0) g_ncinv[bx] = 1.0f / fmaxf(sqrtf(red[0]), 1e-12f);
    } else {
        __shared__ unsigned sh[256];
        float stepf = get_stepf(step_ptr);
        int s = (bx - 64) * 256 + t;
        float age = fmaxf(stepf - at[s], 0.f);
        sh[t] = __float_as_uint(age);
        __syncthreads();
        for (int off = 128; off > 0; off >>= 1) {
            if (t < off && sh[t + off] > sh[t]) sh[t] = sh[t + off];
            __syncthreads();
        }
        if (t == 0) atomicMax(&g_s.age_max_bits, sh[0]);
    }
}

// ---------------- 2: prepB ----------------
__global__ void k_prepB(const float* __restrict__ nc, const float* __restrict__ ec_w) {
    int r = blockIdx.x, t = threadIdx.x;   // 96 blocks x 256 threads
    if (r < 64) {
        float inv = g_ncinv[r];
        for (int k = t; k < DIM; k += 256)
            g_B[r * DIM + k] = wmma::__float_to_tf32(nc[r * DIM + k] * inv);
    } else {
        int j = r - 64;
        for (int k = t; k < DIM; k += 256)
            g_B[r * DIM + k] = wmma::__float_to_tf32(ec_w[(size_t)k * 32 + j]);
    }
}

// ---------------- 3: wmma tf32 GEMM (frozen from R14 best) ----------------
__global__ void __launch_bounds__(256, 2) k_main(const float* __restrict__ mem,
                                                 const float* __restrict__ at,
                                                 const void* __restrict__ step_ptr,
                                                 float* __restrict__ out_mem,
                                                 float* __restrict__ out_nov) {
    extern __shared__ __align__(16) float ring[];
    __shared__ float nsh[128];
    __shared__ int shi[128];
    __shared__ unsigned long long shv[128];
    __shared__ bool sLast;

    const int t = threadIdx.x;
    const int wid = t >> 5, lid = t & 31;
    const int row0 = blockIdx.x * 128;
    const int wr = wid >> 1;
    const int wc = wid & 1;
    const int ra = t >> 3, fa = t & 7;

    uint32_t ring_sm = (uint32_t)__cvta_generic_to_shared(ring);

    wmma::fragment<wmma::accumulator, 16, 16, 8, float> acc[2][3];
#pragma unroll
    for (int i = 0; i < 2; i++)
#pragma unroll
        for (int j = 0; j < 3; j++) wmma::fill_fragment(acc[i][j], 0.0f);
    float sq[4] = {0.f, 0.f, 0.f, 0.f};

#pragma unroll
    for (int st = 0; st < 3; st++) {
        const int kc = st * 32;
        uint32_t base = ring_sm + st * (STAGE_FLOATS * 4);
#pragma unroll
        for (int u = 0; u < 4; u++) {
            int r = ra + 32 * u;
            cp16(base + (uint32_t)((r * LDA + fa * 4) * 4),
                 mem + (size_t)(row0 + r) * DIM + kc + fa * 4);
        }
#pragma unroll
        for (int u = 0; u < 3; u++) {
            int idx = t + 256 * u;
            int r = idx >> 3, f = idx & 7;
            cp16(base + (uint32_t)((128 * LDA + r * LDB + f * 4) * 4),
                 g_B + (size_t)r * DIM + kc + f * 4);
        }
        cp_commit();
    }

    for (int ch = 0; ch < 16; ch++) {
        asm volatile("cp.async.wait_group 2;");
        __syncthreads();
        float* sA = ring + (ch % 3) * STAGE_FLOATS;
        float* sB = sA + 128 * LDA;
        const int kc = ch * 32;
#pragma unroll
        for (int u = 0; u < 4; u++) {
            int r = ra + 32 * u;
            float4 v = *(const float4*)(sA + r * LDA + fa * 4);
            *(float4*)(out_mem + (size_t)(row0 + r) * DIM + kc + fa * 4) = v;
            sq[u] = fmaf(v.x, v.x, fmaf(v.y, v.y, fmaf(v.z, v.z, fmaf(v.w, v.w, sq[u]))));
        }
#pragma unroll
        for (int ks = 0; ks < 4; ks++) {
            const int k0 = ks * 8;
            wmma::fragment<wmma::matrix_a, 16, 16, 8, wmma::precision::tf32, wmma::row_major> af[2];
#pragma unroll
            for (int i = 0; i < 2; i++)
                wmma::load_matrix_sync(af[i], sA + (wr * 32 + i * 16) * LDA + k0, LDA);
#pragma unroll
            for (int j = 0; j < 3; j++) {
                wmma::fragment<wmma::matrix_b, 16, 16, 8, wmma::precision::tf32, wmma::col_major> bf;
                wmma::load_matrix_sync(bf, sB + (wc * 48 + j * 16) * LDB + k0, LDB);
#pragma unroll
                for (int i = 0; i < 2; i++)
                    wmma::mma_sync(acc[i][j], af[i], bf, acc[i][j]);
            }
        }
        __syncthreads();
        if (ch + 3 < 16) {
            const int kn = (ch + 3) * 32;
            uint32_t base = ring_sm + (ch % 3) * (STAGE_FLOATS * 4);
#pragma unroll
            for (int u = 0; u < 4; u++) {
                int r = ra + 32 * u;
                cp16(base + (uint32_t)((r * LDA + fa * 4) * 4),
                     mem + (size_t)(row0 + r) * DIM + kn + fa * 4);
            }
#pragma unroll
            for (int u = 0; u < 3; u++) {
                int idx = t + 256 * u;
                int r = idx >> 3, f = idx & 7;
                cp16(base + (uint32_t)((128 * LDA + r * LDB + f * 4) * 4),
                     g_B + (size_t)r * DIM + kn + f * 4);
            }
        }
        cp_commit();
    }
    asm volatile("cp.async.wait_group 0;");

#pragma unroll
    for (int u = 0; u < 4; u++) {
        float v = sq[u];
        v += __shfl_xor_sync(0xFFFFFFFFu, v, 1);
        v += __shfl_xor_sync(0xFFFFFFFFu, v, 2);
        v += __shfl_xor_sync(0xFFFFFFFFu, v, 4);
        if ((t & 7) == 0) {
            int r = (t >> 3) + 32 * u;
            float n = sqrtf(v);
            nsh[r] = n;
            g_norms[row0 + r] = n;
        }
    }
    __syncthreads();

    if (t < 128) {
        int s = row0 + t;
        float nrm = nsh[t];
        shi[t] = (nrm > 0.5f) ? 1 : 0;
        float amax = __uint_as_float(g_s.age_max_bits);
        float stepf = get_stepf(step_ptr);
        float age = fmaxf(stepf - at[s], 0.f);
        float es = age / (amax + 1e-6f) + (1.0f - sigf(nrm));
        shv[t] = ((unsigned long long)fenc(es) << 32) | (unsigned long long)(0xFFFFFFFFu - (unsigned)s);
    }
    __syncthreads();
    for (int off = 64; off > 0; off >>= 1) {
        if (t < off) {
            shi[t] += shi[t + off];
            if (shv[t + off] > shv[t]) shv[t] = shv[t + off];
        }
        __syncthreads();
    }
    if (t == 0) {
        atomicAdd(&g_s.n_active, shi[0]);
        atomicMax(&g_s.victim_pack, shv[0]);
    }
    __syncthreads();

    float* sD = ring;
#pragma unroll
    for (int i = 0; i < 2; i++)
#pragma unroll
        for (int j = 0; j < 3; j++)
            wmma::store_matrix_sync(sD + (wr * 32 + i * 16) * LDD + wc * 48 + j * 16,
                                    acc[i][j], LDD, wmma::mem_row_major);
    __syncthreads();
    if (wid < 4) {
        int r = wid * 32 + lid;
        int s = row0 + r;
        float inv = 1.0f / fmaxf(nsh[r], 1e-12f);
#pragma unroll
        for (int c4 = 0; c4 < 16; c4++) {
            float4 v4 = *(const float4*)(sD + r * LDD + c4 * 4);
            float vv[4] = {v4.x * inv, v4.y * inv, v4.z * inv, v4.w * inv};
#pragma unroll
            for (int j = 0; j < 4; j++) {
                int c = c4 * 4 + j;
                g_sims[(size_t)c * S_SLOTS + s] = vv[j];
                float m = vv[j];
#pragma unroll
                for (int off = 16; off >= 1; off >>= 1)
                    m = fmaxf(m, __shfl_xor_sync(0xFFFFFFFFu, m, off));
                if (lid == 0) atomicMax(&g_bmax[c], fenc(m));
            }
        }
#pragma unroll
        for (int c = 0; c < 32; c++)
            g_confdot[(size_t)c * S_SLOTS + s] = sD[r * LDD + 64 + c];
    }

    if (t == 0) {
        __threadfence();
        sLast = (atomicAdd(&g_cnt_main, 1u) == (unsigned)(gridDim.x - 1));
    }
    __syncthreads();
    if (sLast) {
        __shared__ float redf[64];
        if (t < 64) {
            float nov = (1.0f - fdec(g_bmax[t])) * 0.5f;
            out_nov[t] = nov;
            redf[t] = nov;
        }
        __syncthreads();
        for (int off = 32; off > 0; off >>= 1) {
            if (t < off) redf[t] += redf[t + off];
            __syncthreads();
        }
        if (t == 0) {
            g_s.nov_mean = redf[0] / (float)BATCH;
            float cap = (float)g_s.n_active / (float)S_SLOTS;
            g_s.do_erase = (cap > 0.85f) ? 1 : 0;
            float dyn = (cap < 0.3f) ? 0.08f : ((cap < 0.6f) ? 0.08f + (cap - 0.3f) * 0.733f
                                                             : 0.3f + (cap - 0.6f));
            g_s.dyn_thr = fminf(fmaxf(dyn, 0.0f), 0.7f);
            g_s.topk_thr = (cap < 0.3f) ? 0.1f : ((cap < 0.6f) ? 0.2f : 0.4f);
            g_s.raw_thr = (cap < 0.3f) ? 0.3f : 0.5f;
            g_s.victim = (int)(0xFFFFFFFFu - (unsigned)(g_s.victim_pack & 0xFFFFFFFFull));
        }
    }
}

// ---------------- 4: store gate (64 blocks, ncu capture slot) ----------------
__global__ void k_store(const float* __restrict__ nc, const float* __restrict__ q,
                        const float* __restrict__ sr_w1, const float* __restrict__ sr_b1,
                        const float* __restrict__ sr_g,  const float* __restrict__ sr_beta,
                        const float* __restrict__ sr_w2, const float* __restrict__ sr_b2,
                        const float* __restrict__ sn_w,  const float* __restrict__ sn_b,
                        const float* __restrict__ sg_w,  const float* __restrict__ sg_b,
                        float* __restrict__ out_store) {
    int b = blockIdx.x, t = threadIdx.x;   // 64 blocks x 256 threads
    __shared__ float comb[1024];
    __shared__ float hpart[4][256];
    __shared__ float rh[256];
    __shared__ float red[256];
    __shared__ float r2part[2][128];
    __shared__ float nfpart[2][128];
    for (int i = t; i < 512; i += 256) {
        comb[i] = nc[b * 512 + i];
        comb[512 + i] = q[b * 512 + i];
    }
    __syncthreads();
    int ks = t >> 6, cg = t & 63;
    {
        float4 a = make_float4(0.f, 0.f, 0.f, 0.f);
        const float* wp = sr_w1 + 4 * cg;
        for (int k = ks * 256; k < ks * 256 + 256; k++) {
            float4 w = *(const float4*)(wp + (size_t)k * 256);
            float x = comb[k];
            a.x = fmaf(x, w.x, a.x); a.y = fmaf(x, w.y, a.y);
            a.z = fmaf(x, w.z, a.z); a.w = fmaf(x, w.w, a.w);
        }
        ((float4*)&hpart[ks][0])[cg] = a;
    }
    __syncthreads();
    float h = hpart[0][t] + hpart[1][t] + hpart[2][t] + hpart[3][t] + sr_b1[t];
    red[t] = h; __syncthreads();
    for (int off = 128; off > 0; off >>= 1) { if (t < off) red[t] += red[t + off]; __syncthreads(); }
    float m = red[0] / 256.0f; __syncthreads();
    float d = h - m;
    red[t] = d * d; __syncthreads();
    for (int off = 128; off > 0; off >>= 1) { if (t < off) red[t] += red[t + off]; __syncthreads(); }
    float var = red[0] / 256.0f; __syncthreads();
    float hn = d * rsqrtf(var + 1e-5f) * sr_g[t] + sr_beta[t];
    rh[t] = fmaxf(hn, 0.f);
    __syncthreads();
    {
        int ks2 = t >> 7, c = t & 127;
        float a = 0.f;
        for (int k = ks2 * 128; k < ks2 * 128 + 128; k++)
            a = fmaf(rh[k], sr_w2[(size_t)k * 128 + c], a);
        r2part[ks2][c] = a;
    }
    {
        int ks2 = t >> 7, c = t & 127;
        float a = 0.f;
        for (int k = ks2 * 256; k < ks2 * 256 + 256; k++)
            a = fmaf(comb[k], sn_w[(size_t)k * 128 + c], a);
        nfpart[ks2][c] = a;
    }
    __syncthreads();
    float val = 0.f;
    if (t < 128) {
        float r = fmaxf(r2part[0][t] + r2part[1][t] + sr_b2[t], 0.f);
        float nf = sigf(nfpart[0][t] + nfpart[1][t] + sn_b[t]);
        val = (r + nf) * sg_w[t];
    }
    red[t] = val; __syncthreads();
    for (int off = 128; off > 0; off >>= 1) { if (t < off) red[t] += red[t + off]; __syncthreads(); }
    if (t == 0) {
        float sc = sigf(red[0] + sg_b[0]);
        g_storev[b] = sc;
        out_store[b] = sc;
    }
}

// ---------------- 5: erase + scan + merge (frozen from R14) ----------------
__global__ void k_scan_er(const float* __restrict__ at, const void* __restrict__ step_ptr,
                          const float* __restrict__ el_w, const float* __restrict__ el_b,
                          const float* __restrict__ ec_b,
                          const float* __restrict__ eg_w, const float* __restrict__ eg_b) {
    int bx = blockIdx.x, t = threadIdx.x;   // 512 blocks x 256 threads
    int de = g_s.do_erase, vic = g_s.victim;
    float stepf = get_stepf(step_ptr);
    __shared__ bool sLast;

    {
        __shared__ unsigned shm[128];
        __shared__ unsigned long long pm[128];
        __shared__ unsigned long long pa[128];
        if (t < 128) {
            int s = bx * 128 + t;
            float atv = at[s];
            bool zv = (de && s == vic);
            if (zv) atv = -99999.0f;
            float x = (stepf - atv) * 0.001f;
            float acc = eg_b[0];
#pragma unroll
            for (int j = 0; j < 32; j++) {
                float lru = fmaxf(fmaf(x, el_w[j], el_b[j]), 0.f);
                float c = zv ? 0.f : g_confdot[(size_t)j * S_SLOTS + s];
                float conf = sigf(c + ec_b[j]);
                acc += lru * eg_w[j] + conf * eg_w[32 + j];
            }
            float e = sigf(acc);
            g_erase[s] = e;
            float sa = stepf - atv;
            g_slotage[s] = sa;
            bool recent = (atv >= 0.f) && (sa < 3.f);
            float mp = recent ? 0.f : e;
            g_maskedpre[s] = mp;
            unsigned idxe = 0xFFFFFFFFu - (unsigned)s;
            shm[t] = __float_as_uint(mp);
            pm[t] = ((unsigned long long)fenc(mp) << 32) | (unsigned long long)idxe;
            pa[t] = ((unsigned long long)fenc(sa) << 32) | (unsigned long long)idxe;
        }
        __syncthreads();
        for (int off = 64; off > 0; off >>= 1) {
            if (t < off) {
                if (shm[t + off] > shm[t]) shm[t] = shm[t + off];
                if (pm[t + off] > pm[t]) pm[t] = pm[t + off];
                if (pa[t + off] > pa[t]) pa[t] = pa[t + off];
            }
            __syncthreads();
        }
        if (t == 0) {
            atomicMax(&g_s.masked_max_bits, shm[0]);
            atomicMax(&g_s.wpack_m, pm[0]);
            atomicMax(&g_s.wpack_a, pa[0]);
        }
        __syncthreads();
    }

    {
        int b = bx >> 3, oc = bx & 7;
        int base = oc * 8192;
        float nm = g_s.nov_mean;
        float v0 = -FLT_MAX, v1 = -FLT_MAX, v2 = -FLT_MAX;
        int i0 = 0x7FFFFFFF, i1 = 0x7FFFFFFF, i2 = 0x7FFFFFFF;
        int cnt = 0;
        const float* row = g_sims + (size_t)b * S_SLOTS;
        for (int s = base + t; s < base + 8192; s += 256) {
            float vraw = row[s];
            if ((nm > 1.0f - vraw) && (g_norms[s] > 0.5f)) cnt++;
            float v = (de && s == vic) ? 0.f : vraw;
            if (better(v, s, v2, i2)) {
                if (better(v, s, v1, i1)) {
                    if (better(v, s, v0, i0)) { v2=v1;i2=i1; v1=v0;i1=i0; v0=v;i0=s; }
                    else                      { v2=v1;i2=i1; v1=v; i1=s; }
                } else                        { v2=v; i2=s; }
            }
        }
        __shared__ float sv[256 * 3];
        __shared__ int   si[256 * 3];
        __shared__ float mv[96];
        __shared__ int   mi[96];
        __shared__ int   sc[256];
        sv[t*3+0]=v0; sv[t*3+1]=v1; sv[t*3+2]=v2;
        si[t*3+0]=i0; si[t*3+1]=i1; si[t*3+2]=i2;
        sc[t] = cnt;
        __syncthreads();
        for (int off = 128; off > 0; off >>= 1) { if (t < off) sc[t] += sc[t + off]; __syncthreads(); }
        if (t < 32) {
            float w0=-FLT_MAX,w1=-FLT_MAX,w2=-FLT_MAX;
            int j0=0x7FFFFFFF,j1=0x7FFFFFFF,j2=0x7FFFFFFF;
            for (int e = t * 24; e < t * 24 + 24; e++) {
                float v = sv[e]; int s = si[e];
                if (better(v, s, w2, j2)) {
                    if (better(v, s, w1, j1)) {
                        if (better(v, s, w0, j0)) { w2=w1;j2=j1; w1=w0;j1=j0; w0=v;j0=s; }
                        else                      { w2=w1;j2=j1; w1=v; j1=s; }
                    } else                        { w2=v; j2=s; }
                }
            }
            mv[t*3+0]=w0; mv[t*3+1]=w1; mv[t*3+2]=w2;
            mi[t*3+0]=j0; mi[t*3+1]=j1; mi[t*3+2]=j2;
        }
        __syncthreads();
        if (t == 0) {
            atomicAdd(&g_s.cond_count, sc[0]);
            float w0=-FLT_MAX,w1=-FLT_MAX,w2=-FLT_MAX; int j0=0x7FFFFFFF,j1=0x7FFFFFFF,j2=0x7FFFFFFF;
            for (int e = 0; e < 96; e++) {
                float v = mv[e]; int s = mi[e];
                if (better(v, s, w2, j2)) {
                    if (better(v, s, w1, j1)) {
                        if (better(v, s, w0, j0)) { w2=w1;j2=j1; w1=w0;j1=j0; w0=v;j0=s; }
                        else                      { w2=w1;j2=j1; w1=v; j1=s; }
                    } else                        { w2=v; j2=s; }
                }
            }
            int o = (b * 8 + oc) * 3;
            g_p3v[o+0]=w0; g_p3v[o+1]=w1; g_p3v[o+2]=w2;
            g_p3i[o+0]=j0; g_p3i[o+1]=j1; g_p3i[o+2]=j2;
        }
    }

    if (t == 0) {
        __threadfence();
        sLast = (atomicAdd(&g_cnt_scan, 1u) == (unsigned)(gridDim.x - 1));
    }
    __syncthreads();
    if (sLast && t < 64) {
        int b = t;
        float w0=-FLT_MAX,w1=-FLT_MAX,w2=-FLT_MAX;
        int j0=0x7FFFFFFF,j1=0x7FFFFFFF,j2=0x7FFFFFFF;
        for (int e = 0; e < 24; e++) {
            float v = g_p3v[b*24+e]; int s = g_p3i[b*24+e];
            if (better(v, s, w2, j2)) {
                if (better(v, s, w1, j1)) {
                    if (better(v, s, w0, j0)) { w2=w1;j2=j1; w1=w0;j1=j0; w0=v;j0=s; }
                    else                      { w2=w1;j2=j1; w1=v; j1=s; }
                } else                        { w2=v; j2=s; }
            }
        }
        g_tv[b*3+0]=w0; g_tv[b*3+1]=w1; g_tv[b*3+2]=w2;
        g_ti[b*3+0]=j0; g_ti[b*3+1]=j1; g_ti[b*3+2]=j2;
    }
}

// ---------------- 6: pair MLPs + last-block finalize (frozen from R14) ----------------
__global__ void k_pair(const float* __restrict__ nc, const float* __restrict__ mem,
                       const float* __restrict__ dd_w1, const float* __restrict__ dd_b1,
                       const float* __restrict__ dd_w2, const float* __restrict__ dd_b2,
                       const float* __restrict__ ds_w1, const float* __restrict__ ds_b1,
                       const float* __restrict__ ds_w2, const float* __restrict__ ds_b2,
                       float* __restrict__ out_mem) {
    __shared__ float pr[4][1024];
    __shared__ float2 part[4][4][2][64];
    __shared__ float red[256];
    __shared__ bool sLast;
    int t = threadIdx.x;   // 256
    int pg = blockIdx.x >> 1, ch = blockIdx.x & 1;
    int p0 = pg * 4;
    int de = g_s.do_erase, vic = g_s.victim;
    for (int p = 0; p < 4; p++) {
        int pi = p0 + p;
        int b = pi / 3;
        int ti = g_ti[pi];
        bool z = (de && ti == vic);
        for (int i = t; i < 512; i += 256) {
            pr[p][i] = nc[b * 512 + i];
            pr[p][512 + i] = z ? 0.f : mem[(size_t)ti * 512 + i];
        }
    }
    __syncthreads();
    int ks = t >> 6, cg = t & 63;
    int colG = ch * 128 + 2 * cg;
    unsigned long long aD[4] = {0ull,0ull,0ull,0ull};
    unsigned long long aS[4] = {0ull,0ull,0ull,0ull};
    const float* dp = dd_w1 + colG;
    const float* sp = ds_w1 + colG;
    for (int k = ks * 256; k < ks * 256 + 256; k++) {
        unsigned long long wd = *(const unsigned long long*)(dp + (size_t)k * 256);
        unsigned long long ws = *(const unsigned long long*)(sp + (size_t)k * 256);
#pragma unroll
        for (int p = 0; p < 4; p++) {
            float x = pr[p][k];
            unsigned xi = __float_as_uint(x);
            unsigned long long x2;
            asm("mov.b64 %0, {%1, %2};" : "=l"(x2) : "r"(xi), "r"(xi));
            asm("fma.rn.f32x2 %0, %1, %2, %0;" : "+l"(aD[p]) : "l"(x2), "l"(wd));
            asm("fma.rn.f32x2 %0, %1, %2, %0;" : "+l"(aS[p]) : "l"(x2), "l"(ws));
        }
    }
#pragma unroll
    for (int p = 0; p < 4; p++) {
        part[ks][p][0][cg] = *reinterpret_cast<float2*>(&aD[p]);
        part[ks][p][1][cg] = *reinterpret_cast<float2*>(&aS[p]);
    }
    __syncthreads();
    float vals[8];
    if (t < 128) {
        int c = t;
        int cG = ch * 128 + c;
#pragma unroll
        for (int p = 0; p < 4; p++) {
#pragma unroll
            for (int net = 0; net < 2; net++) {
                float s = 0.f;
#pragma unroll
                for (int kq = 0; kq < 4; kq++) {
                    float2 f2 = part[kq][p][net][c >> 1];
                    s += (c & 1) ? f2.y : f2.x;
                }
                s += net ? ds_b1[cG] : dd_b1[cG];
                s = fmaxf(s, 0.f) * (net ? ds_w2[cG] : dd_w2[cG]);
                vals[p * 2 + net] = s;
            }
        }
    }
    for (int pn = 0; pn < 8; pn++) {
        __syncthreads();
        red[t] = (t < 128) ? vals[pn] : 0.f;
        __syncthreads();
        for (int off = 128; off > 0; off >>= 1) { if (t < off) red[t] += red[t + off]; __syncthreads(); }
        if (t == 0) atomicAdd(&g_pairacc[(p0 + (pn >> 1)) * 2 + (pn & 1)], red[0]);
    }

    if (t == 0) {
        __threadfence();
        sLast = (atomicAdd(&g_cnt_pair, 1u) == (unsigned)(gridDim.x - 1));
    }
    __syncthreads();
    if (sLast) {
        if (t < BATCH * 3) {
            float prob = sigf(g_pairacc[t * 2 + 0] + dd_b2[0]);
            float st   = sigf(g_pairacc[t * 2 + 1] + ds_b2[0]);
            g_strength[t] = st;
            float tv = g_tv[t];
            g_apply[t] = (tv > 0.7f && tv < 0.99f && prob > 0.5f) ? 1 : 0;
        }
        __syncthreads();
        if (t == 0) {
            float ssum = 0.f;
            for (int b = 0; b < BATCH; b++) ssum += g_storev[b];
            float smean = ssum / (float)BATCH;
            int na = g_s.n_active;
            int nam = na > 1 ? na : 1;
            float perc = (na > 0) ? ((float)g_s.cond_count / (64.0f * (float)nam)) : 1.0f;
            bool base = smean > g_s.raw_thr;
            bool novok = g_s.nov_mean > g_s.dyn_thr;
            bool topok = perc > g_s.topk_thr;
            bool ss = base && novok && topok;
            if (de && !novok) ss = false;
            g_s.should_store = ss ? 1 : 0;
            int usa = (__uint_as_float(g_s.masked_max_bits) <= 0.0f) ? 1 : 0;
            g_s.use_slotage = usa;
            unsigned long long wp = usa ? g_s.wpack_a : g_s.wpack_m;
            int wmax = (int)(0xFFFFFFFFu - (unsigned)(wp & 0xFFFFFFFFull));
            int wi = de ? vic : wmax;
            g_s.write_idx = wi;
            int n = 0;
            if (de) g_chg[n++] = vic;
            for (int p = 0; p < BATCH * 3; p++) {
                if (g_apply[p]) {
                    int r = g_ti[p];
                    int found = 0;
                    for (int j = 0; j < n; j++) if (g_chg[j] == r) { found = 1; break; }
                    if (!found) g_chg[n++] = r;
                }
            }
            if (ss) {
                int r = wi, found = 0;
                for (int j = 0; j < n; j++) if (g_chg[j] == r) { found = 1; break; }
                if (!found) g_chg[n++] = r;
            }
            g_nchg = n;
        }
        __syncthreads();
        for (int dd = 0; dd < 2; dd++) {
            int d = t + 256 * dd;
            float nc0 = nc[d];
            float v = nc0;
            for (int k = 0; k < 3; k++) {
                if (g_apply[k]) {
                    int r = g_ti[k];
                    float g = (de && r == vic) ? 0.f : mem[(size_t)r * 512 + d];
                    float st = g_strength[k];
                    float avg = 0.5f * (nc0 + g);
                    v = (1.f - st) * nc0 + st * avg;
                }
            }
            g_drifted0[d] = v;
            if (de) out_mem[(size_t)vic * 512 + d] = 0.f;
            for (int k = 0; k < 3; k++) {
                for (int b = 0; b < BATCH; b++) {
                    int p = b * 3 + k;
                    if (g_apply[p]) {
                        int r = g_ti[p];
                        float g = (de && r == vic) ? 0.f : mem[(size_t)r * 512 + d];
                        float st = g_strength[p];
                        float ncv = nc[b * 512 + d];
                        float avg = 0.5f * (ncv + g);
                        out_mem[(size_t)r * 512 + d] = (1.f - st) * g + st * avg;
                    }
                }
            }
            if (g_s.should_store) out_mem[(size_t)g_s.write_idx * 512 + d] = g_drifted0[d];
        }
    }
}

// ---------------- 7: outputs + rc + accumulator reset for next replay ----------------
__global__ void k_out_rc(const float* __restrict__ at, const void* __restrict__ step_ptr,
                         const float* __restrict__ mem, const float* __restrict__ out_mem,
                         float* __restrict__ out_at, float* __restrict__ out_erase,
                         float* __restrict__ out_rc) {
    int bx = blockIdx.x, t = threadIdx.x;
    int s = bx * 256 + t;
    float atv = at[s];
    if (g_s.do_erase && s == g_s.victim) atv = -99999.0f;
    if (g_s.should_store && s == g_s.write_idx) atv = get_stepf(step_ptr);
    out_at[s] = atv;
    float mf = g_s.use_slotage ? g_slotage[s] : g_maskedpre[s];
    out_erase[s] = (g_s.should_store && !g_s.do_erase) ? mf : g_erase[s];
    if (bx == 0) {
        __shared__ float sh[256];
        int n = g_nchg;
        float acc = 0.f;
        for (int j = t; j < n * 512; j += 256) {
            int r = g_chg[j >> 9];
            int d = j & 511;
            acc += fabsf(out_mem[(size_t)r * 512 + d] - mem[(size_t)r * 512 + d]);
        }
        sh[t] = acc; __syncthreads();
        for (int off = 128; off > 0; off >>= 1) { if (t < off) sh[t] += sh[t + off]; __syncthreads(); }
        if (t == 0) out_rc[0] = sh[0] / ((float)S_SLOTS * (float)DIM);
        // ---- reset accumulators for next replay (deterministic per replay) ----
        if (t == 0) {
            g_s.n_active = 0;
            g_s.age_max_bits = 0u;
            g_s.victim_pack = 0ull;
            g_s.cond_count = 0;
            g_s.masked_max_bits = 0u;
            g_s.wpack_m = 0ull;
            g_s.wpack_a = 0ull;
            g_cnt_main = 0u; g_cnt_scan = 0u; g_cnt_pair = 0u;
        }
        if (t < BATCH) g_bmax[t] = 0u;
        for (int i = t; i < BATCH * 3 * 2; i += 256) g_pairacc[i] = 0.f;
    }
}

// ---------------- launch ----------------
extern "C" void kernel_launch(void* const* d_in, const int* in_sizes, int n_in,
                              void* d_out, int out_size) {
    bool dictOrder = (in_sizes[4] == 1);
    const float* nc   = (const float*)d_in[0];
    const float* q    = (const float*)d_in[1];
    const float* mem  = (const float*)d_in[2];
    const float* at   = (const float*)d_in[3];
    int base = dictOrder ? 5 : 4;
    const float* sr_w1 = (const float*)d_in[base + 0];
    const float* sr_b1 = (const float*)d_in[base + 1];
    const float* sr_g  = (const float*)d_in[base + 2];
    const float* sr_be = (const float*)d_in[base + 3];
    const float* sr_w2 = (const float*)d_in[base + 4];
    const float* sr_b2 = (const float*)d_in[base + 5];
    const float* sn_w  = (const float*)d_in[base + 6];
    const float* sn_b  = (const float*)d_in[base + 7];
    const float* sg_w  = (const float*)d_in[base + 8];
    const float* sg_b  = (const float*)d_in[base + 9];
    const float* el_w  = (const float*)d_in[base + 10];
    const float* el_b  = (const float*)d_in[base + 11];
    const float* ec_w  = (const float*)d_in[base + 12];
    const float* ec_b  = (const float*)d_in[base + 13];
    const float* eg_w  = (const float*)d_in[base + 14];
    const float* eg_b  = (const float*)d_in[base + 15];
    const float* dd_w1 = (const float*)d_in[base + 16];
    const float* dd_b1 = (const float*)d_in[base + 17];
    const float* dd_w2 = (const float*)d_in[base + 18];
    const float* dd_b2 = (const float*)d_in[base + 19];
    const float* ds_w1 = (const float*)d_in[base + 20];
    const float* ds_b1 = (const float*)d_in[base + 21];
    const float* ds_w2 = (const float*)d_in[base + 22];
    const float* ds_b2 = (const float*)d_in[base + 23];
    const void*  step  = dictOrder ? d_in[4] : d_in[28];

    float* out_mem   = (float*)d_out;
    float* out_at    = out_mem + (size_t)S_SLOTS * DIM;
    float* out_erase = out_at + S_SLOTS;
    float* out_store = out_erase + S_SLOTS;
    float* out_nov   = out_store + BATCH;
    float* out_rc    = out_nov + BATCH;

    cudaFuncSetAttribute(k_main, cudaFuncAttributeMaxDynamicSharedMemorySize, RING_BYTES);

    k_na_am<<<64 + S_SLOTS / 256, 256>>>(nc, at, step);             // 1
    k_prepB<<<96, 256>>>(nc, ec_w);                                 // 2
    k_main<<<S_SLOTS / 128, 256, RING_BYTES>>>(mem, at, step, out_mem, out_nov); // 3
    k_store<<<BATCH, 256>>>(nc, q, sr_w1, sr_b1, sr_g, sr_be,       // 4 <- ncu slot
                            sr_w2, sr_b2, sn_w, sn_b, sg_w, sg_b, out_store);
    k_scan_er<<<512, 256>>>(at, step, el_w, el_b, ec_b, eg_w, eg_b);// 5
    k_pair<<<96, 256>>>(nc, mem, dd_w1, dd_b1, dd_w2, dd_b2,        // 6
                        ds_w1, ds_b1, ds_w2, ds_b2, out_mem);
    k_out_rc<<<S_SLOTS / 256, 256>>>(at, step, mem, out_mem, out_at, out_erase, out_rc); // 7
}

// round 16
// speedup vs baseline: 1.0626x; 1.0104x over previous
#include <cuda_runtime.h>
#include <math.h>
#include <float.h>
#include <stdint.h>
#include <mma.h>

using namespace nvcuda;

#define S_SLOTS 65536
#define DIM     512
#define BATCH   64

#define LDA  36
#define LDB  36
#define LDD  100
#define STAGE_FLOATS ((128 + 96) * 36)
#define RING_FLOATS  (3 * STAGE_FLOATS)
#define RING_BYTES   (RING_FLOATS * 4)

// ---------------- device scratch (zero-init at load; reset by k_out_rc each replay) ----------------
__device__ float g_ncinv[BATCH];
__device__ float g_B[96 * DIM];
__device__ float g_sims[(size_t)BATCH * S_SLOTS];
__device__ float g_confdot[(size_t)32 * S_SLOTS];    // [c][s]
__device__ float g_norms[S_SLOTS];
__device__ float g_erase[S_SLOTS];
__device__ float g_maskedpre[S_SLOTS];
__device__ float g_slotage[S_SLOTS];
__device__ unsigned g_bmax[BATCH];
__device__ float g_storev[BATCH];
__device__ int   g_ti[BATCH * 3];
__device__ float g_tv[BATCH * 3];
__device__ float g_p3v[BATCH * 8 * 3];
__device__ int   g_p3i[BATCH * 8 * 3];
__device__ float g_pairacc[BATCH * 3 * 2];
__device__ float g_strength[BATCH * 3];
__device__ int   g_apply[BATCH * 3];
__device__ float g_drifted0[DIM];
__device__ int   g_chg[256];
__device__ int   g_nchg;
__device__ unsigned g_cnt_main, g_cnt_scan, g_cnt_pair;

struct Scalars {
    int   n_active;
    unsigned int age_max_bits;
    unsigned long long victim_pack;
    int   cond_count;
    unsigned int masked_max_bits;
    unsigned long long wpack_m;
    unsigned long long wpack_a;
    int   do_erase;
    int   victim;
    float dyn_thr, topk_thr, raw_thr;
    float nov_mean;
    int   should_store;
    int   use_slotage;
    int   write_idx;
};
__device__ Scalars g_s;

__device__ __forceinline__ float get_stepf(const void* p) {
    int   iv = *(const int*)p;
    float fv = *(const float*)p;
    return (iv > 0 && iv < 100000000) ? (float)iv : fv;
}
__device__ __forceinline__ float sigf(float x) { return 1.0f / (1.0f + __expf(-x)); }
__device__ __forceinline__ unsigned fenc(float f) {
    unsigned u = __float_as_uint(f);
    return (u & 0x80000000u) ? ~u : (u | 0x80000000u);
}
__device__ __forceinline__ float fdec(unsigned u) {
    return (u & 0x80000000u) ? __uint_as_float(u ^ 0x80000000u) : __uint_as_float(~u);
}
__device__ __forceinline__ bool better(float av, int ai, float bv, int bi) {
    return (av > bv) || (av == bv && ai < bi);
}
__device__ __forceinline__ void cp16(uint32_t dst_smem, const void* src) {
    asm volatile("cp.async.ca.shared.global [%0], [%1], 16;" :: "r"(dst_smem), "l"(src));
}
__device__ __forceinline__ void cp_commit() {
    asm volatile("cp.async.commit_group;");
}

// ---------------- 1: norm_a + agemax ----------------
__global__ void k_na_am(const float* __restrict__ nc, const float* __restrict__ at,
                        const void* __restrict__ step_ptr) {
    int bx = blockIdx.x, t = threadIdx.x;   // 256 threads
    if (bx < 64) {
        __shared__ float red[256];
        float v0 = nc[bx * 512 + t];
        float v1 = nc[bx * 512 + 256 + t];
        red[t] = v0 * v0 + v1 * v1;
        __syncthreads();
        for (int off = 128; off > 0; off >>= 1) { if (t < off) red[t] += red[t + off]; __syncthreads(); }
        if (t == 0) g_ncinv[bx] = 1.0f / fmaxf(sqrtf(red[0]), 1e-12f);
    } else {
        __shared__ unsigned sh[256];
        float stepf = get_stepf(step_ptr);
        int s = (bx - 64) * 256 + t;
        float age = fmaxf(stepf - at[s], 0.f);
        sh[t] = __float_as_uint(age);
        __syncthreads();
        for (int off = 128; off > 0; off >>= 1) {
            if (t < off && sh[t + off] > sh[t]) sh[t] = sh[t + off];
            __syncthreads();
        }
        if (t == 0) atomicMax(&g_s.age_max_bits, sh[0]);
    }
}

// ---------------- 2: prepB ----------------
__global__ void k_prepB(const float* __restrict__ nc, const float* __restrict__ ec_w) {
    int r = blockIdx.x, t = threadIdx.x;   // 96 blocks x 256 threads
    if (r < 64) {
        float inv = g_ncinv[r];
        for (int k = t; k < DIM; k += 256)
            g_B[r * DIM + k] = wmma::__float_to_tf32(nc[r * DIM + k] * inv);
    } else {
        int j = r - 64;
        for (int k = t; k < DIM; k += 256)
            g_B[r * DIM + k] = wmma::__float_to_tf32(ec_w[(size_t)k * 32 + j]);
    }
}

// ---------------- 3: wmma tf32 GEMM (frozen) ----------------
__global__ void __launch_bounds__(256, 2) k_main(const float* __restrict__ mem,
                                                 const float* __restrict__ at,
                                                 const void* __restrict__ step_ptr,
                                                 float* __restrict__ out_mem,
                                                 float* __restrict__ out_nov) {
    extern __shared__ __align__(16) float ring[];
    __shared__ float nsh[128];
    __shared__ int shi[128];
    __shared__ unsigned long long shv[128];
    __shared__ bool sLast;

    const int t = threadIdx.x;
    const int wid = t >> 5, lid = t & 31;
    const int row0 = blockIdx.x * 128;
    const int wr = wid >> 1;
    const int wc = wid & 1;
    const int ra = t >> 3, fa = t & 7;

    uint32_t ring_sm = (uint32_t)__cvta_generic_to_shared(ring);

    wmma::fragment<wmma::accumulator, 16, 16, 8, float> acc[2][3];
#pragma unroll
    for (int i = 0; i < 2; i++)
#pragma unroll
        for (int j = 0; j < 3; j++) wmma::fill_fragment(acc[i][j], 0.0f);
    float sq[4] = {0.f, 0.f, 0.f, 0.f};

#pragma unroll
    for (int st = 0; st < 3; st++) {
        const int kc = st * 32;
        uint32_t base = ring_sm + st * (STAGE_FLOATS * 4);
#pragma unroll
        for (int u = 0; u < 4; u++) {
            int r = ra + 32 * u;
            cp16(base + (uint32_t)((r * LDA + fa * 4) * 4),
                 mem + (size_t)(row0 + r) * DIM + kc + fa * 4);
        }
#pragma unroll
        for (int u = 0; u < 3; u++) {
            int idx = t + 256 * u;
            int r = idx >> 3, f = idx & 7;
            cp16(base + (uint32_t)((128 * LDA + r * LDB + f * 4) * 4),
                 g_B + (size_t)r * DIM + kc + f * 4);
        }
        cp_commit();
    }

    for (int ch = 0; ch < 16; ch++) {
        asm volatile("cp.async.wait_group 2;");
        __syncthreads();
        float* sA = ring + (ch % 3) * STAGE_FLOATS;
        float* sB = sA + 128 * LDA;
        const int kc = ch * 32;
#pragma unroll
        for (int u = 0; u < 4; u++) {
            int r = ra + 32 * u;
            float4 v = *(const float4*)(sA + r * LDA + fa * 4);
            *(float4*)(out_mem + (size_t)(row0 + r) * DIM + kc + fa * 4) = v;
            sq[u] = fmaf(v.x, v.x, fmaf(v.y, v.y, fmaf(v.z, v.z, fmaf(v.w, v.w, sq[u]))));
        }
#pragma unroll
        for (int ks = 0; ks < 4; ks++) {
            const int k0 = ks * 8;
            wmma::fragment<wmma::matrix_a, 16, 16, 8, wmma::precision::tf32, wmma::row_major> af[2];
#pragma unroll
            for (int i = 0; i < 2; i++)
                wmma::load_matrix_sync(af[i], sA + (wr * 32 + i * 16) * LDA + k0, LDA);
#pragma unroll
            for (int j = 0; j < 3; j++) {
                wmma::fragment<wmma::matrix_b, 16, 16, 8, wmma::precision::tf32, wmma::col_major> bf;
                wmma::load_matrix_sync(bf, sB + (wc * 48 + j * 16) * LDB + k0, LDB);
#pragma unroll
                for (int i = 0; i < 2; i++)
                    wmma::mma_sync(acc[i][j], af[i], bf, acc[i][j]);
            }
        }
        __syncthreads();
        if (ch + 3 < 16) {
            const int kn = (ch + 3) * 32;
            uint32_t base = ring_sm + (ch % 3) * (STAGE_FLOATS * 4);
#pragma unroll
            for (int u = 0; u < 4; u++) {
                int r = ra + 32 * u;
                cp16(base + (uint32_t)((r * LDA + fa * 4) * 4),
                     mem + (size_t)(row0 + r) * DIM + kn + fa * 4);
            }
#pragma unroll
            for (int u = 0; u < 3; u++) {
                int idx = t + 256 * u;
                int r = idx >> 3, f = idx & 7;
                cp16(base + (uint32_t)((128 * LDA + r * LDB + f * 4) * 4),
                     g_B + (size_t)r * DIM + kn + f * 4);
            }
        }
        cp_commit();
    }
    asm volatile("cp.async.wait_group 0;");

#pragma unroll
    for (int u = 0; u < 4; u++) {
        float v = sq[u];
        v += __shfl_xor_sync(0xFFFFFFFFu, v, 1);
        v += __shfl_xor_sync(0xFFFFFFFFu, v, 2);
        v += __shfl_xor_sync(0xFFFFFFFFu, v, 4);
        if ((t & 7) == 0) {
            int r = (t >> 3) + 32 * u;
            float n = sqrtf(v);
            nsh[r] = n;
            g_norms[row0 + r] = n;
        }
    }
    __syncthreads();

    if (t < 128) {
        int s = row0 + t;
        float nrm = nsh[t];
        shi[t] = (nrm > 0.5f) ? 1 : 0;
        float amax = __uint_as_float(g_s.age_max_bits);
        float stepf = get_stepf(step_ptr);
        float age = fmaxf(stepf - at[s], 0.f);
        float es = age / (amax + 1e-6f) + (1.0f - sigf(nrm));
        shv[t] = ((unsigned long long)fenc(es) << 32) | (unsigned long long)(0xFFFFFFFFu - (unsigned)s);
    }
    __syncthreads();
    for (int off = 64; off > 0; off >>= 1) {
        if (t < off) {
            shi[t] += shi[t + off];
            if (shv[t + off] > shv[t]) shv[t] = shv[t + off];
        }
        __syncthreads();
    }
    if (t == 0) {
        atomicAdd(&g_s.n_active, shi[0]);
        atomicMax(&g_s.victim_pack, shv[0]);
    }
    __syncthreads();

    float* sD = ring;
#pragma unroll
    for (int i = 0; i < 2; i++)
#pragma unroll
        for (int j = 0; j < 3; j++)
            wmma::store_matrix_sync(sD + (wr * 32 + i * 16) * LDD + wc * 48 + j * 16,
                                    acc[i][j], LDD, wmma::mem_row_major);
    __syncthreads();
    if (wid < 4) {
        int r = wid * 32 + lid;
        int s = row0 + r;
        float inv = 1.0f / fmaxf(nsh[r], 1e-12f);
#pragma unroll
        for (int c4 = 0; c4 < 16; c4++) {
            float4 v4 = *(const float4*)(sD + r * LDD + c4 * 4);
            float vv[4] = {v4.x * inv, v4.y * inv, v4.z * inv, v4.w * inv};
#pragma unroll
            for (int j = 0; j < 4; j++) {
                int c = c4 * 4 + j;
                g_sims[(size_t)c * S_SLOTS + s] = vv[j];
                float m = vv[j];
#pragma unroll
                for (int off = 16; off >= 1; off >>= 1)
                    m = fmaxf(m, __shfl_xor_sync(0xFFFFFFFFu, m, off));
                if (lid == 0) atomicMax(&g_bmax[c], fenc(m));
            }
        }
#pragma unroll
        for (int c = 0; c < 32; c++)
            g_confdot[(size_t)c * S_SLOTS + s] = sD[r * LDD + 64 + c];
    }

    if (t == 0) {
        __threadfence();
        sLast = (atomicAdd(&g_cnt_main, 1u) == (unsigned)(gridDim.x - 1));
    }
    __syncthreads();
    if (sLast) {
        __shared__ float redf[64];
        if (t < 64) {
            float nov = (1.0f - fdec(g_bmax[t])) * 0.5f;
            out_nov[t] = nov;
            redf[t] = nov;
        }
        __syncthreads();
        for (int off = 32; off > 0; off >>= 1) {
            if (t < off) redf[t] += redf[t + off];
            __syncthreads();
        }
        if (t == 0) {
            g_s.nov_mean = redf[0] / (float)BATCH;
            float cap = (float)g_s.n_active / (float)S_SLOTS;
            g_s.do_erase = (cap > 0.85f) ? 1 : 0;
            float dyn = (cap < 0.3f) ? 0.08f : ((cap < 0.6f) ? 0.08f + (cap - 0.3f) * 0.733f
                                                             : 0.3f + (cap - 0.6f));
            g_s.dyn_thr = fminf(fmaxf(dyn, 0.0f), 0.7f);
            g_s.topk_thr = (cap < 0.3f) ? 0.1f : ((cap < 0.6f) ? 0.2f : 0.4f);
            g_s.raw_thr = (cap < 0.3f) ? 0.3f : 0.5f;
            g_s.victim = (int)(0xFFFFFFFFu - (unsigned)(g_s.victim_pack & 0xFFFFFFFFull));
        }
    }
}

// ---------------- 4: store gate, deep-MLP restructure (ncu capture slot) ----------------
__global__ void k_store(const float* __restrict__ nc, const float* __restrict__ q,
                        const float* __restrict__ sr_w1, const float* __restrict__ sr_b1,
                        const float* __restrict__ sr_g,  const float* __restrict__ sr_beta,
                        const float* __restrict__ sr_w2, const float* __restrict__ sr_b2,
                        const float* __restrict__ sn_w,  const float* __restrict__ sn_b,
                        const float* __restrict__ sg_w,  const float* __restrict__ sg_b,
                        float* __restrict__ out_store) {
    int b = blockIdx.x, t = threadIdx.x;   // 64 blocks x 256 threads
    __shared__ float comb[1024];
    __shared__ float hpart[8][256];
    __shared__ float rh[256];
    __shared__ float red[256];
    __shared__ float r2part[8][128];
    __shared__ float nfpart[8][128];
    for (int i = t; i < 512; i += 256) {
        comb[i] = nc[b * 512 + i];
        comb[512 + i] = q[b * 512 + i];
    }
    __syncthreads();
    const int cg = t & 31, ks = t >> 5;   // warp-uniform ks -> comb[k] broadcast
    // phase 1: 8 cols/thread (cg*8..), 128-k slice, 2 indep float4 loads/iter
    {
        float4 a0 = make_float4(0.f, 0.f, 0.f, 0.f);
        float4 a1 = make_float4(0.f, 0.f, 0.f, 0.f);
        const float* wp = sr_w1 + cg * 8;
#pragma unroll 4
        for (int k = ks * 128; k < ks * 128 + 128; k++) {
            float x = comb[k];
            float4 w0 = *(const float4*)(wp + (size_t)k * 256);
            float4 w1 = *(const float4*)(wp + (size_t)k * 256 + 4);
            a0.x = fmaf(x, w0.x, a0.x); a0.y = fmaf(x, w0.y, a0.y);
            a0.z = fmaf(x, w0.z, a0.z); a0.w = fmaf(x, w0.w, a0.w);
            a1.x = fmaf(x, w1.x, a1.x); a1.y = fmaf(x, w1.y, a1.y);
            a1.z = fmaf(x, w1.z, a1.z); a1.w = fmaf(x, w1.w, a1.w);
        }
        ((float4*)&hpart[ks][0])[cg * 2]     = a0;
        ((float4*)&hpart[ks][0])[cg * 2 + 1] = a1;
    }
    __syncthreads();
    float h = sr_b1[t];
#pragma unroll
    for (int sl = 0; sl < 8; sl++) h += hpart[sl][t];
    red[t] = h; __syncthreads();
    for (int off = 128; off > 0; off >>= 1) { if (t < off) red[t] += red[t + off]; __syncthreads(); }
    float m = red[0] / 256.0f; __syncthreads();
    float d = h - m;
    red[t] = d * d; __syncthreads();
    for (int off = 128; off > 0; off >>= 1) { if (t < off) red[t] += red[t + off]; __syncthreads(); }
    float var = red[0] / 256.0f; __syncthreads();
    float hn = d * rsqrtf(var + 1e-5f) * sr_g[t] + sr_beta[t];
    rh[t] = fmaxf(hn, 0.f);
    __syncthreads();
    // phase 2a: rel = rh @ sr_w2 — 4 cols/thread, 32-k slice
    {
        float4 a = make_float4(0.f, 0.f, 0.f, 0.f);
        const float* wp = sr_w2 + cg * 4;
#pragma unroll 4
        for (int k = ks * 32; k < ks * 32 + 32; k++) {
            float x = rh[k];
            float4 w = *(const float4*)(wp + (size_t)k * 128);
            a.x = fmaf(x, w.x, a.x); a.y = fmaf(x, w.y, a.y);
            a.z = fmaf(x, w.z, a.z); a.w = fmaf(x, w.w, a.w);
        }
        ((float4*)&r2part[ks][0])[cg] = a;
    }
    // phase 2b: nf = comb @ sn_w — 4 cols/thread, 64-k slice
    {
        float4 a = make_float4(0.f, 0.f, 0.f, 0.f);
        const float* wp = sn_w + cg * 4;
#pragma unroll 4
        for (int k = ks * 64; k < ks * 64 + 64; k++) {
            float x = comb[k];
            float4 w = *(const float4*)(wp + (size_t)k * 128);
            a.x = fmaf(x, w.x, a.x); a.y = fmaf(x, w.y, a.y);
            a.z = fmaf(x, w.z, a.z); a.w = fmaf(x, w.w, a.w);
        }
        ((float4*)&nfpart[ks][0])[cg] = a;
    }
    __syncthreads();
    float val = 0.f;
    if (t < 128) {
        float r = sr_b2[t];
#pragma unroll
        for (int sl = 0; sl < 8; sl++) r += r2part[sl][t];
        r = fmaxf(r, 0.f);
        float nf = sn_b[t];
#pragma unroll
        for (int sl = 0; sl < 8; sl++) nf += nfpart[sl][t];
        nf = sigf(nf);
        val = (r + nf) * sg_w[t];
    }
    red[t] = val; __syncthreads();
    for (int off = 128; off > 0; off >>= 1) { if (t < off) red[t] += red[t + off]; __syncthreads(); }
    if (t == 0) {
        float sc = sigf(red[0] + sg_b[0]);
        g_storev[b] = sc;
        out_store[b] = sc;
    }
}

// ---------------- 5: erase + scan + merge (frozen) ----------------
__global__ void k_scan_er(const float* __restrict__ at, const void* __restrict__ step_ptr,
                          const float* __restrict__ el_w, const float* __restrict__ el_b,
                          const float* __restrict__ ec_b,
                          const float* __restrict__ eg_w, const float* __restrict__ eg_b) {
    int bx = blockIdx.x, t = threadIdx.x;   // 512 blocks x 256 threads
    int de = g_s.do_erase, vic = g_s.victim;
    float stepf = get_stepf(step_ptr);
    __shared__ bool sLast;

    {
        __shared__ unsigned shm[128];
        __shared__ unsigned long long pm[128];
        __shared__ unsigned long long pa[128];
        if (t < 128) {
            int s = bx * 128 + t;
            float atv = at[s];
            bool zv = (de && s == vic);
            if (zv) atv = -99999.0f;
            float x = (stepf - atv) * 0.001f;
            float acc = eg_b[0];
#pragma unroll
            for (int j = 0; j < 32; j++) {
                float lru = fmaxf(fmaf(x, el_w[j], el_b[j]), 0.f);
                float c = zv ? 0.f : g_confdot[(size_t)j * S_SLOTS + s];
                float conf = sigf(c + ec_b[j]);
                acc += lru * eg_w[j] + conf * eg_w[32 + j];
            }
            float e = sigf(acc);
            g_erase[s] = e;
            float sa = stepf - atv;
            g_slotage[s] = sa;
            bool recent = (atv >= 0.f) && (sa < 3.f);
            float mp = recent ? 0.f : e;
            g_maskedpre[s] = mp;
            unsigned idxe = 0xFFFFFFFFu - (unsigned)s;
            shm[t] = __float_as_uint(mp);
            pm[t] = ((unsigned long long)fenc(mp) << 32) | (unsigned long long)idxe;
            pa[t] = ((unsigned long long)fenc(sa) << 32) | (unsigned long long)idxe;
        }
        __syncthreads();
        for (int off = 64; off > 0; off >>= 1) {
            if (t < off) {
                if (shm[t + off] > shm[t]) shm[t] = shm[t + off];
                if (pm[t + off] > pm[t]) pm[t] = pm[t + off];
                if (pa[t + off] > pa[t]) pa[t] = pa[t + off];
            }
            __syncthreads();
        }
        if (t == 0) {
            atomicMax(&g_s.masked_max_bits, shm[0]);
            atomicMax(&g_s.wpack_m, pm[0]);
            atomicMax(&g_s.wpack_a, pa[0]);
        }
        __syncthreads();
    }

    {
        int b = bx >> 3, oc = bx & 7;
        int base = oc * 8192;
        float nm = g_s.nov_mean;
        float v0 = -FLT_MAX, v1 = -FLT_MAX, v2 = -FLT_MAX;
        int i0 = 0x7FFFFFFF, i1 = 0x7FFFFFFF, i2 = 0x7FFFFFFF;
        int cnt = 0;
        const float* row = g_sims + (size_t)b * S_SLOTS;
        for (int s = base + t; s < base + 8192; s += 256) {
            float vraw = row[s];
            if ((nm > 1.0f - vraw) && (g_norms[s] > 0.5f)) cnt++;
            float v = (de && s == vic) ? 0.f : vraw;
            if (better(v, s, v2, i2)) {
                if (better(v, s, v1, i1)) {
                    if (better(v, s, v0, i0)) { v2=v1;i2=i1; v1=v0;i1=i0; v0=v;i0=s; }
                    else                      { v2=v1;i2=i1; v1=v; i1=s; }
                } else                        { v2=v; i2=s; }
            }
        }
        __shared__ float sv[256 * 3];
        __shared__ int   si[256 * 3];
        __shared__ float mv[96];
        __shared__ int   mi[96];
        __shared__ int   sc[256];
        sv[t*3+0]=v0; sv[t*3+1]=v1; sv[t*3+2]=v2;
        si[t*3+0]=i0; si[t*3+1]=i1; si[t*3+2]=i2;
        sc[t] = cnt;
        __syncthreads();
        for (int off = 128; off > 0; off >>= 1) { if (t < off) sc[t] += sc[t + off]; __syncthreads(); }
        if (t < 32) {
            float w0=-FLT_MAX,w1=-FLT_MAX,w2=-FLT_MAX;
            int j0=0x7FFFFFFF,j1=0x7FFFFFFF,j2=0x7FFFFFFF;
            for (int e = t * 24; e < t * 24 + 24; e++) {
                float v = sv[e]; int s = si[e];
                if (better(v, s, w2, j2)) {
                    if (better(v, s, w1, j1)) {
                        if (better(v, s, w0, j0)) { w2=w1;j2=j1; w1=w0;j1=j0; w0=v;j0=s; }
                        else                      { w2=w1;j2=j1; w1=v; j1=s; }
                    } else                        { w2=v; j2=s; }
                }
            }
            mv[t*3+0]=w0; mv[t*3+1]=w1; mv[t*3+2]=w2;
            mi[t*3+0]=j0; mi[t*3+1]=j1; mi[t*3+2]=j2;
        }
        __syncthreads();
        if (t == 0) {
            atomicAdd(&g_s.cond_count, sc[0]);
            float w0=-FLT_MAX,w1=-FLT_MAX,w2=-FLT_MAX; int j0=0x7FFFFFFF,j1=0x7FFFFFFF,j2=0x7FFFFFFF;
            for (int e = 0; e < 96; e++) {
                float v = mv[e]; int s = mi[e];
                if (better(v, s, w2, j2)) {
                    if (better(v, s, w1, j1)) {
                        if (better(v, s, w0, j0)) { w2=w1;j2=j1; w1=w0;j1=j0; w0=v;j0=s; }
                        else                      { w2=w1;j2=j1; w1=v; j1=s; }
                    } else                        { w2=v; j2=s; }
                }
            }
            int o = (b * 8 + oc) * 3;
            g_p3v[o+0]=w0; g_p3v[o+1]=w1; g_p3v[o+2]=w2;
            g_p3i[o+0]=j0; g_p3i[o+1]=j1; g_p3i[o+2]=j2;
        }
    }

    if (t == 0) {
        __threadfence();
        sLast = (atomicAdd(&g_cnt_scan, 1u) == (unsigned)(gridDim.x - 1));
    }
    __syncthreads();
    if (sLast && t < 64) {
        int b = t;
        float w0=-FLT_MAX,w1=-FLT_MAX,w2=-FLT_MAX;
        int j0=0x7FFFFFFF,j1=0x7FFFFFFF,j2=0x7FFFFFFF;
        for (int e = 0; e < 24; e++) {
            float v = g_p3v[b*24+e]; int s = g_p3i[b*24+e];
            if (better(v, s, w2, j2)) {
                if (better(v, s, w1, j1)) {
                    if (better(v, s, w0, j0)) { w2=w1;j2=j1; w1=w0;j1=j0; w0=v;j0=s; }
                    else                      { w2=w1;j2=j1; w1=v; j1=s; }
                } else                        { w2=v; j2=s; }
            }
        }
        g_tv[b*3+0]=w0; g_tv[b*3+1]=w1; g_tv[b*3+2]=w2;
        g_ti[b*3+0]=j0; g_ti[b*3+1]=j1; g_ti[b*3+2]=j2;
    }
}

// ---------------- 6: pair MLPs + last-block finalize (frozen) ----------------
__global__ void k_pair(const float* __restrict__ nc, const float* __restrict__ mem,
                       const float* __restrict__ dd_w1, const float* __restrict__ dd_b1,
                       const float* __restrict__ dd_w2, const float* __restrict__ dd_b2,
                       const float* __restrict__ ds_w1, const float* __restrict__ ds_b1,
                       const float* __restrict__ ds_w2, const float* __restrict__ ds_b2,
                       float* __restrict__ out_mem) {
    __shared__ float pr[4][1024];
    __shared__ float2 part[4][4][2][64];
    __shared__ float red[256];
    __shared__ bool sLast;
    int t = threadIdx.x;   // 256
    int pg = blockIdx.x >> 1, ch = blockIdx.x & 1;
    int p0 = pg * 4;
    int de = g_s.do_erase, vic = g_s.victim;
    for (int p = 0; p < 4; p++) {
        int pi = p0 + p;
        int b = pi / 3;
        int ti = g_ti[pi];
        bool z = (de && ti == vic);
        for (int i = t; i < 512; i += 256) {
            pr[p][i] = nc[b * 512 + i];
            pr[p][512 + i] = z ? 0.f : mem[(size_t)ti * 512 + i];
        }
    }
    __syncthreads();
    int ks = t >> 6, cg = t & 63;
    int colG = ch * 128 + 2 * cg;
    unsigned long long aD[4] = {0ull,0ull,0ull,0ull};
    unsigned long long aS[4] = {0ull,0ull,0ull,0ull};
    const float* dp = dd_w1 + colG;
    const float* sp = ds_w1 + colG;
    for (int k = ks * 256; k < ks * 256 + 256; k++) {
        unsigned long long wd = *(const unsigned long long*)(dp + (size_t)k * 256);
        unsigned long long ws = *(const unsigned long long*)(sp + (size_t)k * 256);
#pragma unroll
        for (int p = 0; p < 4; p++) {
            float x = pr[p][k];
            unsigned xi = __float_as_uint(x);
            unsigned long long x2;
            asm("mov.b64 %0, {%1, %2};" : "=l"(x2) : "r"(xi), "r"(xi));
            asm("fma.rn.f32x2 %0, %1, %2, %0;" : "+l"(aD[p]) : "l"(x2), "l"(wd));
            asm("fma.rn.f32x2 %0, %1, %2, %0;" : "+l"(aS[p]) : "l"(x2), "l"(ws));
        }
    }
#pragma unroll
    for (int p = 0; p < 4; p++) {
        part[ks][p][0][cg] = *reinterpret_cast<float2*>(&aD[p]);
        part[ks][p][1][cg] = *reinterpret_cast<float2*>(&aS[p]);
    }
    __syncthreads();
    float vals[8];
    if (t < 128) {
        int c = t;
        int cG = ch * 128 + c;
#pragma unroll
        for (int p = 0; p < 4; p++) {
#pragma unroll
            for (int net = 0; net < 2; net++) {
                float s = 0.f;
#pragma unroll
                for (int kq = 0; kq < 4; kq++) {
                    float2 f2 = part[kq][p][net][c >> 1];
                    s += (c & 1) ? f2.y : f2.x;
                }
                s += net ? ds_b1[cG] : dd_b1[cG];
                s = fmaxf(s, 0.f) * (net ? ds_w2[cG] : dd_w2[cG]);
                vals[p * 2 + net] = s;
            }
        }
    }
    for (int pn = 0; pn < 8; pn++) {
        __syncthreads();
        red[t] = (t < 128) ? vals[pn] : 0.f;
        __syncthreads();
        for (int off = 128; off > 0; off >>= 1) { if (t < off) red[t] += red[t + off]; __syncthreads(); }
        if (t == 0) atomicAdd(&g_pairacc[(p0 + (pn >> 1)) * 2 + (pn & 1)], red[0]);
    }

    if (t == 0) {
        __threadfence();
        sLast = (atomicAdd(&g_cnt_pair, 1u) == (unsigned)(gridDim.x - 1));
    }
    __syncthreads();
    if (sLast) {
        if (t < BATCH * 3) {
            float prob = sigf(g_pairacc[t * 2 + 0] + dd_b2[0]);
            float st   = sigf(g_pairacc[t * 2 + 1] + ds_b2[0]);
            g_strength[t] = st;
            float tv = g_tv[t];
            g_apply[t] = (tv > 0.7f && tv < 0.99f && prob > 0.5f) ? 1 : 0;
        }
        __syncthreads();
        if (t == 0) {
            float ssum = 0.f;
            for (int b = 0; b < BATCH; b++) ssum += g_storev[b];
            float smean = ssum / (float)BATCH;
            int na = g_s.n_active;
            int nam = na > 1 ? na : 1;
            float perc = (na > 0) ? ((float)g_s.cond_count / (64.0f * (float)nam)) : 1.0f;
            bool base = smean > g_s.raw_thr;
            bool novok = g_s.nov_mean > g_s.dyn_thr;
            bool topok = perc > g_s.topk_thr;
            bool ss = base && novok && topok;
            if (de && !novok) ss = false;
            g_s.should_store = ss ? 1 : 0;
            int usa = (__uint_as_float(g_s.masked_max_bits) <= 0.0f) ? 1 : 0;
            g_s.use_slotage = usa;
            unsigned long long wp = usa ? g_s.wpack_a : g_s.wpack_m;
            int wmax = (int)(0xFFFFFFFFu - (unsigned)(wp & 0xFFFFFFFFull));
            int wi = de ? vic : wmax;
            g_s.write_idx = wi;
            int n = 0;
            if (de) g_chg[n++] = vic;
            for (int p = 0; p < BATCH * 3; p++) {
                if (g_apply[p]) {
                    int r = g_ti[p];
                    int found = 0;
                    for (int j = 0; j < n; j++) if (g_chg[j] == r) { found = 1; break; }
                    if (!found) g_chg[n++] = r;
                }
            }
            if (ss) {
                int r = wi, found = 0;
                for (int j = 0; j < n; j++) if (g_chg[j] == r) { found = 1; break; }
                if (!found) g_chg[n++] = r;
            }
            g_nchg = n;
        }
        __syncthreads();
        for (int dd = 0; dd < 2; dd++) {
            int d = t + 256 * dd;
            float nc0 = nc[d];
            float v = nc0;
            for (int k = 0; k < 3; k++) {
                if (g_apply[k]) {
                    int r = g_ti[k];
                    float g = (de && r == vic) ? 0.f : mem[(size_t)r * 512 + d];
                    float st = g_strength[k];
                    float avg = 0.5f * (nc0 + g);
                    v = (1.f - st) * nc0 + st * avg;
                }
            }
            g_drifted0[d] = v;
            if (de) out_mem[(size_t)vic * 512 + d] = 0.f;
            for (int k = 0; k < 3; k++) {
                for (int b = 0; b < BATCH; b++) {
                    int p = b * 3 + k;
                    if (g_apply[p]) {
                        int r = g_ti[p];
                        float g = (de && r == vic) ? 0.f : mem[(size_t)r * 512 + d];
                        float st = g_strength[p];
                        float ncv = nc[b * 512 + d];
                        float avg = 0.5f * (ncv + g);
                        out_mem[(size_t)r * 512 + d] = (1.f - st) * g + st * avg;
                    }
                }
            }
            if (g_s.should_store) out_mem[(size_t)g_s.write_idx * 512 + d] = g_drifted0[d];
        }
    }
}

// ---------------- 7: outputs + rc + accumulator reset ----------------
__global__ void k_out_rc(const float* __restrict__ at, const void* __restrict__ step_ptr,
                         const float* __restrict__ mem, const float* __restrict__ out_mem,
                         float* __restrict__ out_at, float* __restrict__ out_erase,
                         float* __restrict__ out_rc) {
    int bx = blockIdx.x, t = threadIdx.x;
    int s = bx * 256 + t;
    float atv = at[s];
    if (g_s.do_erase && s == g_s.victim) atv = -99999.0f;
    if (g_s.should_store && s == g_s.write_idx) atv = get_stepf(step_ptr);
    out_at[s] = atv;
    float mf = g_s.use_slotage ? g_slotage[s] : g_maskedpre[s];
    out_erase[s] = (g_s.should_store && !g_s.do_erase) ? mf : g_erase[s];
    if (bx == 0) {
        __shared__ float sh[256];
        int n = g_nchg;
        float acc = 0.f;
        for (int j = t; j < n * 512; j += 256) {
            int r = g_chg[j >> 9];
            int d = j & 511;
            acc += fabsf(out_mem[(size_t)r * 512 + d] - mem[(size_t)r * 512 + d]);
        }
        sh[t] = acc; __syncthreads();
        for (int off = 128; off > 0; off >>= 1) { if (t < off) sh[t] += sh[t + off]; __syncthreads(); }
        if (t == 0) out_rc[0] = sh[0] / ((float)S_SLOTS * (float)DIM);
        if (t == 0) {
            g_s.n_active = 0;
            g_s.age_max_bits = 0u;
            g_s.victim_pack = 0ull;
            g_s.cond_count = 0;
            g_s.masked_max_bits = 0u;
            g_s.wpack_m = 0ull;
            g_s.wpack_a = 0ull;
            g_cnt_main = 0u; g_cnt_scan = 0u; g_cnt_pair = 0u;
        }
        if (t < BATCH) g_bmax[t] = 0u;
        for (int i = t; i < BATCH * 3 * 2; i += 256) g_pairacc[i] = 0.f;
    }
}

// ---------------- launch ----------------
extern "C" void kernel_launch(void* const* d_in, const int* in_sizes, int n_in,
                              void* d_out, int out_size) {
    bool dictOrder = (in_sizes[4] == 1);
    const float* nc   = (const float*)d_in[0];
    const float* q    = (const float*)d_in[1];
    const float* mem  = (const float*)d_in[2];
    const float* at   = (const float*)d_in[3];
    int base = dictOrder ? 5 : 4;
    const float* sr_w1 = (const float*)d_in[base + 0];
    const float* sr_b1 = (const float*)d_in[base + 1];
    const float* sr_g  = (const float*)d_in[base + 2];
    const float* sr_be = (const float*)d_in[base + 3];
    const float* sr_w2 = (const float*)d_in[base + 4];
    const float* sr_b2 = (const float*)d_in[base + 5];
    const float* sn_w  = (const float*)d_in[base + 6];
    const float* sn_b  = (const float*)d_in[base + 7];
    const float* sg_w  = (const float*)d_in[base + 8];
    const float* sg_b  = (const float*)d_in[base + 9];
    const float* el_w  = (const float*)d_in[base + 10];
    const float* el_b  = (const float*)d_in[base + 11];
    const float* ec_w  = (const float*)d_in[base + 12];
    const float* ec_b  = (const float*)d_in[base + 13];
    const float* eg_w  = (const float*)d_in[base + 14];
    const float* eg_b  = (const float*)d_in[base + 15];
    const float* dd_w1 = (const float*)d_in[base + 16];
    const float* dd_b1 = (const float*)d_in[base + 17];
    const float* dd_w2 = (const float*)d_in[base + 18];
    const float* dd_b2 = (const float*)d_in[base + 19];
    const float* ds_w1 = (const float*)d_in[base + 20];
    const float* ds_b1 = (const float*)d_in[base + 21];
    const float* ds_w2 = (const float*)d_in[base + 22];
    const float* ds_b2 = (const float*)d_in[base + 23];
    const void*  step  = dictOrder ? d_in[4] : d_in[28];

    float* out_mem   = (float*)d_out;
    float* out_at    = out_mem + (size_t)S_SLOTS * DIM;
    float* out_erase = out_at + S_SLOTS;
    float* out_store = out_erase + S_SLOTS;
    float* out_nov   = out_store + BATCH;
    float* out_rc    = out_nov + BATCH;

    cudaFuncSetAttribute(k_main, cudaFuncAttributeMaxDynamicSharedMemorySize, RING_BYTES);

    k_na_am<<<64 + S_SLOTS / 256, 256>>>(nc, at, step);             // 1
    k_prepB<<<96, 256>>>(nc, ec_w);                                 // 2
    k_main<<<S_SLOTS / 128, 256, RING_BYTES>>>(mem, at, step, out_mem, out_nov); // 3
    k_store<<<BATCH, 256>>>(nc, q, sr_w1, sr_b1, sr_g, sr_be,       // 4 <- ncu slot
                            sr_w2, sr_b2, sn_w, sn_b, sg_w, sg_b, out_store);
    k_scan_er<<<512, 256>>>(at, step, el_w, el_b, ec_b, eg_w, eg_b);// 5
    k_pair<<<96, 256>>>(nc, mem, dd_w1, dd_b1, dd_w2, dd_b2,        // 6
                        ds_w1, ds_b1, ds_w2, ds_b2, out_mem);
    k_out_rc<<<S_SLOTS / 256, 256>>>(at, step, mem, out_mem, out_at, out_erase, out_rc); // 7
}